// round 1
// baseline (speedup 1.0000x reference)
#include <cuda_runtime.h>
#include <math.h>

#define Bv  2
#define Sv  2048
#define Dv  2048
#define Hv  16
#define DKv 128
#define Mv  (Bv*Sv)   // 4096

// Scratch (allocation-free rule: __device__ globals)
__device__ float g_Q[(size_t)Bv*Sv*Dv];    // 32MB: post-RoPE Q
__device__ float g_ctx[(size_t)Bv*Sv*Dv];  // 32MB: attention context

// ---------------------------------------------------------------------------
// C[M,N] = A[M,K] * W[N,K]^T   (M=4096, N=K=2048), optional fused RoPE
// 128x128 block tile, BK=16, 256 threads, 8x8 per thread (cols split 4+4)
// ---------------------------------------------------------------------------
template<bool ROPE>
__global__ __launch_bounds__(256)
void gemm_kernel(const float* __restrict__ A, const float* __restrict__ W,
                 const float* __restrict__ fc, const float* __restrict__ fs,
                 float* __restrict__ C)
{
    __shared__ float As[128][17];   // [row][k], pad to kill store conflicts
    __shared__ float Bs[128][17];   // [col][k]

    const int tid = threadIdx.x;
    const int tx  = tid & 15;       // 0..15 -> col groups
    const int ty  = tid >> 4;       // 0..15 -> 8 rows each
    const int row0 = blockIdx.y * 128;
    const int col0 = blockIdx.x * 128;

    float acc[8][8];
    #pragma unroll
    for (int i = 0; i < 8; i++)
        #pragma unroll
        for (int j = 0; j < 8; j++) acc[i][j] = 0.0f;

    const int lrow = tid >> 1;          // 0..127
    const int lk   = (tid & 1) * 8;     // 0 or 8

    const float* Aptr = A + (size_t)(row0 + lrow) * Dv + lk;
    const float* Wptr = W + (size_t)(col0 + lrow) * Dv + lk;

    for (int kt = 0; kt < Dv; kt += 16) {
        float4 a0 = *(const float4*)(Aptr + kt);
        float4 a1 = *(const float4*)(Aptr + kt + 4);
        float4 b0 = *(const float4*)(Wptr + kt);
        float4 b1 = *(const float4*)(Wptr + kt + 4);
        As[lrow][lk+0] = a0.x; As[lrow][lk+1] = a0.y;
        As[lrow][lk+2] = a0.z; As[lrow][lk+3] = a0.w;
        As[lrow][lk+4] = a1.x; As[lrow][lk+5] = a1.y;
        As[lrow][lk+6] = a1.z; As[lrow][lk+7] = a1.w;
        Bs[lrow][lk+0] = b0.x; Bs[lrow][lk+1] = b0.y;
        Bs[lrow][lk+2] = b0.z; Bs[lrow][lk+3] = b0.w;
        Bs[lrow][lk+4] = b1.x; Bs[lrow][lk+5] = b1.y;
        Bs[lrow][lk+6] = b1.z; Bs[lrow][lk+7] = b1.w;
        __syncthreads();

        #pragma unroll
        for (int kk = 0; kk < 16; kk++) {
            float a[8], b[8];
            #pragma unroll
            for (int i = 0; i < 8; i++) a[i] = As[ty*8 + i][kk];        // broadcast
            #pragma unroll
            for (int j = 0; j < 4; j++) {
                b[j]   = Bs[tx*4 + j][kk];                               // conflict-free
                b[4+j] = Bs[64 + tx*4 + j][kk];
            }
            #pragma unroll
            for (int i = 0; i < 8; i++)
                #pragma unroll
                for (int j = 0; j < 8; j++) acc[i][j] = fmaf(a[i], b[j], acc[i][j]);
        }
        __syncthreads();
    }

    // epilogue (optionally fused RoPE), float4 stores
    #pragma unroll
    for (int i = 0; i < 8; i++) {
        const int gr   = row0 + ty*8 + i;
        const int srow = gr & (Sv - 1);
        #pragma unroll
        for (int g = 0; g < 2; g++) {
            const int gc = col0 + g*64 + tx*4;
            float v0 = acc[i][g*4+0], v1 = acc[i][g*4+1];
            float v2 = acc[i][g*4+2], v3 = acc[i][g*4+3];
            if (ROPE) {
                const int d  = gc & (DKv - 1);   // 4-aligned -> proper pairs
                const int ip = d >> 1;
                float c0 = fc[srow*64 + ip],     s0 = fs[srow*64 + ip];
                float c1 = fc[srow*64 + ip + 1], s1 = fs[srow*64 + ip + 1];
                float o0 = v0*c0 - v1*s0;
                float o1 = v0*s0 + v1*c0;
                float o2 = v2*c1 - v3*s1;
                float o3 = v2*s1 + v3*c1;
                v0 = o0; v1 = o1; v2 = o2; v3 = o3;
            }
            float4 r; r.x = v0; r.y = v1; r.z = v2; r.w = v3;
            *(float4*)(C + (size_t)gr * Dv + gc) = r;
        }
    }
}

// ---------------------------------------------------------------------------
// Flash attention, fp32, online softmax, strict causal.
// Per block: 64 q-rows of one (b,h). 256 threads.
// Thread grid 16x16: rows r0=ty*4 (both phases), scores cols tx*4,
// PV cols {tx*4, 64+tx*4}.
// ---------------------------------------------------------------------------
__global__ __launch_bounds__(256)
void attn_kernel(const float* __restrict__ Q, const float* __restrict__ Kp,
                 const float* __restrict__ Vp, float* __restrict__ ctx)
{
    extern __shared__ float sm[];
    float* Qs = sm;                   // [64][129]
    float* Ks = Qs + 64*129;          // [64][129]
    float* Vs = Ks + 64*129;          // [64][128]
    float* Ps = Vs + 64*128;          // [64][65]

    const int tid = threadIdx.x;
    const int tx  = tid & 15;
    const int ty  = tid >> 4;
    const int q0  = blockIdx.x * 64;
    const int h   = blockIdx.y;
    const int b   = blockIdx.z;
    const size_t hoff = (size_t)h * DKv;

    // load Q tile -> Qs (stride 129)
    {
        const int r  = tid >> 2;
        const int c0 = (tid & 3) * 32;
        const float* src = Q + ((size_t)(b*Sv + q0 + r)) * Dv + hoff + c0;
        #pragma unroll
        for (int u = 0; u < 8; u++) {
            float4 v = *(const float4*)(src + u*4);
            Qs[r*129 + c0 + u*4 + 0] = v.x;
            Qs[r*129 + c0 + u*4 + 1] = v.y;
            Qs[r*129 + c0 + u*4 + 2] = v.z;
            Qs[r*129 + c0 + u*4 + 3] = v.w;
        }
    }

    float m_run[4], l_run[4], acc[4][8];
    #pragma unroll
    for (int i = 0; i < 4; i++) {
        m_run[i] = -1e30f; l_run[i] = 0.0f;
        #pragma unroll
        for (int j = 0; j < 8; j++) acc[i][j] = 0.0f;
    }

    const int r0 = ty * 4;
    const float scale = 0.08838834764831845f;   // 1/sqrt(128)
    const int n_kt = (q0 >> 6) + 1;             // causal: tiles up to diagonal

    for (int kt = 0; kt < n_kt; kt++) {
        const int k0 = kt * 64;
        __syncthreads();   // previous PV done before Ks/Vs/Ps reuse
        {
            const int r  = tid >> 2;
            const int c0 = (tid & 3) * 32;
            const float* ksrc = Kp + ((size_t)(b*Sv + k0 + r)) * Dv + hoff + c0;
            const float* vsrc = Vp + ((size_t)(b*Sv + k0 + r)) * Dv + hoff + c0;
            #pragma unroll
            for (int u = 0; u < 8; u++) {
                float4 kv = *(const float4*)(ksrc + u*4);
                Ks[r*129 + c0 + u*4 + 0] = kv.x;
                Ks[r*129 + c0 + u*4 + 1] = kv.y;
                Ks[r*129 + c0 + u*4 + 2] = kv.z;
                Ks[r*129 + c0 + u*4 + 3] = kv.w;
                float4 vv = *(const float4*)(vsrc + u*4);
                *(float4*)(Vs + r*128 + c0 + u*4) = vv;
            }
        }
        __syncthreads();

        // scores: 4 rows x 4 cols per thread over dk=128
        float sc[4][4];
        #pragma unroll
        for (int i = 0; i < 4; i++)
            #pragma unroll
            for (int j = 0; j < 4; j++) sc[i][j] = 0.0f;

        #pragma unroll 8
        for (int k = 0; k < 128; k++) {
            float a[4], bq[4];
            #pragma unroll
            for (int i = 0; i < 4; i++) a[i]  = Qs[(r0 + i)*129 + k];
            #pragma unroll
            for (int j = 0; j < 4; j++) bq[j] = Ks[(tx*4 + j)*129 + k];
            #pragma unroll
            for (int i = 0; i < 4; i++)
                #pragma unroll
                for (int j = 0; j < 4; j++) sc[i][j] = fmaf(a[i], bq[j], sc[i][j]);
        }

        // scale + causal mask (only diagonal tile can violate causality)
        float tm[4];
        #pragma unroll
        for (int i = 0; i < 4; i++) {
            const int gq = q0 + r0 + i;
            #pragma unroll
            for (int j = 0; j < 4; j++) {
                sc[i][j] *= scale;
                if (k0 + tx*4 + j > gq) sc[i][j] = -1e30f;
            }
            tm[i] = fmaxf(fmaxf(sc[i][0], sc[i][1]), fmaxf(sc[i][2], sc[i][3]));
        }
        // row reduce across the 16 lanes of the row-group (width 16)
        #pragma unroll
        for (int i = 0; i < 4; i++) {
            #pragma unroll
            for (int off = 8; off > 0; off >>= 1)
                tm[i] = fmaxf(tm[i], __shfl_xor_sync(0xffffffffu, tm[i], off, 16));
        }

        float alpha[4], ts[4];
        #pragma unroll
        for (int i = 0; i < 4; i++) {
            float mn = fmaxf(m_run[i], tm[i]);
            alpha[i] = __expf(m_run[i] - mn);
            m_run[i] = mn;
            float s = 0.0f;
            #pragma unroll
            for (int j = 0; j < 4; j++) {
                sc[i][j] = __expf(sc[i][j] - mn);   // masked -> exp(-1e30) == 0
                s += sc[i][j];
            }
            ts[i] = s;
        }
        #pragma unroll
        for (int i = 0; i < 4; i++) {
            #pragma unroll
            for (int off = 8; off > 0; off >>= 1)
                ts[i] += __shfl_xor_sync(0xffffffffu, ts[i], off, 16);
            l_run[i] = l_run[i] * alpha[i] + ts[i];
        }

        // store P tile
        #pragma unroll
        for (int i = 0; i < 4; i++)
            #pragma unroll
            for (int j = 0; j < 4; j++)
                Ps[(r0 + i)*65 + tx*4 + j] = sc[i][j];
        __syncthreads();

        // rescale accumulators, then P @ V
        #pragma unroll
        for (int i = 0; i < 4; i++)
            #pragma unroll
            for (int j = 0; j < 8; j++) acc[i][j] *= alpha[i];

        #pragma unroll 4
        for (int jj = 0; jj < 64; jj++) {
            float p[4];
            #pragma unroll
            for (int i = 0; i < 4; i++) p[i] = Ps[(r0 + i)*65 + jj];   // broadcast
            float4 v0 = *(const float4*)(Vs + jj*128 + tx*4);
            float4 v1 = *(const float4*)(Vs + jj*128 + 64 + tx*4);
            #pragma unroll
            for (int i = 0; i < 4; i++) {
                acc[i][0] = fmaf(p[i], v0.x, acc[i][0]);
                acc[i][1] = fmaf(p[i], v0.y, acc[i][1]);
                acc[i][2] = fmaf(p[i], v0.z, acc[i][2]);
                acc[i][3] = fmaf(p[i], v0.w, acc[i][3]);
                acc[i][4] = fmaf(p[i], v1.x, acc[i][4]);
                acc[i][5] = fmaf(p[i], v1.y, acc[i][5]);
                acc[i][6] = fmaf(p[i], v1.z, acc[i][6]);
                acc[i][7] = fmaf(p[i], v1.w, acc[i][7]);
            }
        }
    }

    // epilogue: ctx = acc / l
    #pragma unroll
    for (int i = 0; i < 4; i++) {
        const float inv = 1.0f / l_run[i];
        const int gq = q0 + r0 + i;
        float* dst = ctx + ((size_t)(b*Sv + gq)) * Dv + hoff;
        float4 o0; o0.x = acc[i][0]*inv; o0.y = acc[i][1]*inv;
                   o0.z = acc[i][2]*inv; o0.w = acc[i][3]*inv;
        float4 o1; o1.x = acc[i][4]*inv; o1.y = acc[i][5]*inv;
                   o1.z = acc[i][6]*inv; o1.w = acc[i][7]*inv;
        *(float4*)(dst + tx*4)      = o0;
        *(float4*)(dst + 64 + tx*4) = o1;
    }
}

// ---------------------------------------------------------------------------
extern "C" void kernel_launch(void* const* d_in, const int* in_sizes, int n_in,
                              void* d_out, int out_size)
{
    const float* x  = (const float*)d_in[0];
    const float* fc = (const float*)d_in[1];
    const float* fs = (const float*)d_in[2];
    // d_in[3] = mask (unused: -1e9 mask == strict causal in f32)
    const float* Wq = (const float*)d_in[4];
    const float* Wk = (const float*)d_in[5];
    const float* Wv = (const float*)d_in[6];
    const float* Wo = (const float*)d_in[7];

    float* out  = (float*)d_out;                    // [B,S,D] attention output
    float* outK = out  + (size_t)Bv*Sv*Dv;          // [B,S,H,dk] post-RoPE K
    float* outV = outK + (size_t)Bv*Sv*Dv;          // [B,S,H,dk] V

    float *Qbuf, *Cbuf;
    cudaGetSymbolAddress((void**)&Qbuf, g_Q);
    cudaGetSymbolAddress((void**)&Cbuf, g_ctx);

    dim3 ggrid(Dv/128, Mv/128);   // (16, 32)
    gemm_kernel<true ><<<ggrid, 256>>>(x, Wq, fc, fs, Qbuf);
    gemm_kernel<true ><<<ggrid, 256>>>(x, Wk, fc, fs, outK);
    gemm_kernel<false><<<ggrid, 256>>>(x, Wv, fc, fs, outV);

    const int smem = (64*129*2 + 64*128 + 64*65) * (int)sizeof(float);  // 115456 B
    cudaFuncSetAttribute(attn_kernel, cudaFuncAttributeMaxDynamicSharedMemorySize, smem);
    attn_kernel<<<dim3(Sv/64, Hv, Bv), 256, smem>>>(Qbuf, outK, outV, Cbuf);

    gemm_kernel<false><<<ggrid, 256>>>(Cbuf, Wo, fc, fs, out);
}

// round 6
// speedup vs baseline: 1.6041x; 1.6041x over previous
#include <cuda_runtime.h>
#include <cuda_bf16.h>
#include <math.h>
#include <stdint.h>

#define Bv  2
#define Sv  2048
#define Dv  2048
#define Hv  16
#define DKv 128
#define Mv  (Bv*Sv)   // 4096

// Scratch (allocation-free rule: __device__ globals)
__device__ float g_Q[(size_t)Mv*Dv];    // 32MB: post-RoPE Q
__device__ float g_ctx[(size_t)Mv*Dv];  // 32MB: attention context

// ---------------------------------------------------------------------------
// helpers
// ---------------------------------------------------------------------------
__device__ __forceinline__ uint32_t smem_u32(const void* p){
    uint32_t a;
    asm("{ .reg .u64 t; cvta.to.shared.u64 t, %1; cvt.u32.u64 %0, t; }" : "=r"(a) : "l"(p));
    return a;
}
__device__ __forceinline__ uint32_t pack_bf2(float x, float y){
    __nv_bfloat162 h = __floats2bfloat162_rn(x, y);
    return *reinterpret_cast<uint32_t*>(&h);
}
__device__ __forceinline__ void ldsm4(uint32_t addr, uint32_t r[4]){
    asm volatile("ldmatrix.sync.aligned.m8n8.x4.shared.b16 {%0,%1,%2,%3}, [%4];"
                 : "=r"(r[0]), "=r"(r[1]), "=r"(r[2]), "=r"(r[3]) : "r"(addr));
}
__device__ __forceinline__ void mma16816(float c[4], const uint32_t a[4], const uint32_t b[2]){
    asm volatile(
        "mma.sync.aligned.m16n8k16.row.col.f32.bf16.bf16.f32 "
        "{%0,%1,%2,%3}, {%4,%5,%6,%7}, {%8,%9}, {%0,%1,%2,%3};"
        : "+f"(c[0]), "+f"(c[1]), "+f"(c[2]), "+f"(c[3])
        : "r"(a[0]), "r"(a[1]), "r"(a[2]), "r"(a[3]), "r"(b[0]), "r"(b[1]));
}

// Convert 16 fp32 -> 16 bf16 hi + 16 bf16 lo, store as 2x uint4 each.
__device__ __forceinline__ void cvt_store16(const float* __restrict__ src,
                                            char* dhi, char* dlo)
{
    uint32_t h[8], l[8];
    #pragma unroll
    for (int u = 0; u < 4; u++) {
        float4 v = ((const float4*)src)[u];
        float hx = __bfloat162float(__float2bfloat16(v.x));
        float hy = __bfloat162float(__float2bfloat16(v.y));
        float hz = __bfloat162float(__float2bfloat16(v.z));
        float hw = __bfloat162float(__float2bfloat16(v.w));
        h[2*u]   = pack_bf2(hx, hy);
        h[2*u+1] = pack_bf2(hz, hw);
        l[2*u]   = pack_bf2(v.x - hx, v.y - hy);
        l[2*u+1] = pack_bf2(v.z - hz, v.w - hw);
    }
    ((uint4*)dhi)[0] = make_uint4(h[0], h[1], h[2], h[3]);
    ((uint4*)dhi)[1] = make_uint4(h[4], h[5], h[6], h[7]);
    ((uint4*)dlo)[0] = make_uint4(l[0], l[1], l[2], l[3]);
    ((uint4*)dlo)[1] = make_uint4(l[4], l[5], l[6], l[7]);
}

// ---------------------------------------------------------------------------
// bf16 mma.sync GEMM with hi/lo split: C[M,N] = A[M,K] * W[N,K]^T (fp32 I/O)
// 128x128 tile, BK=32, 256 threads (8 warps, 2x4), fused RoPE epilogue.
// SMEM per stage: Ah, Al, Wh, Wl each [128][40] bf16 (pad 40 -> LDSM
// conflict-free). Double buffered, one __syncthreads per chunk.
// ---------------------------------------------------------------------------
#define SA      40
#define TILE_B  (128*SA*2)      // 10240 B per matrix tile
#define STAGE_B (4*TILE_B)      // 40960 B
#define GSM_TOTAL (2*STAGE_B)   // 81920 B

template<bool ROPE>
__global__ __launch_bounds__(256, 1)
void gemm_mma(const float* __restrict__ A, const float* __restrict__ W,
              const float* __restrict__ fc, const float* __restrict__ fs,
              float* __restrict__ C)
{
    extern __shared__ __align__(1024) char smem[];
    const int tid  = threadIdx.x;
    const int lane = tid & 31;
    const int wid  = tid >> 5;
    const int wm   = wid >> 2;      // 0..1 (M half)
    const int wn   = wid & 3;       // 0..3 (N quarter)
    const int row0 = blockIdx.y * 128;
    const int col0 = blockIdx.x * 128;

    float acc[4][4][4];
    #pragma unroll
    for (int i = 0; i < 4; i++)
        #pragma unroll
        for (int j = 0; j < 4; j++)
            #pragma unroll
            for (int q = 0; q < 4; q++) acc[i][j][q] = 0.0f;

    // ldmatrix lane addressing
    const int la_r = (lane & 7) + ((lane >> 3) & 1) * 8;   // A: row within 16
    const int la_k = (lane >> 4) * 8;                      // A: k tile offset
    const int lb_c = (lane & 7) + (lane >> 4) * 8;         // B: col within 16
    const int lb_k = ((lane >> 3) & 1) * 8;                // B: k tile offset

    // global load addressing: thread -> (row, 16-wide half of the 32-k chunk)
    const int grow = tid >> 1;
    const int half = tid & 1;
    const float* aG = A + (size_t)(row0 + grow) * Dv + half * 16;
    const float* wG = W + (size_t)(col0 + grow) * Dv + half * 16;
    const int dsto = grow * (SA*2) + half * 32;

    // prologue: chunk 0 -> stage 0
    {
        char* st = smem;
        cvt_store16(aG,      st + dsto,            st + TILE_B   + dsto);
        cvt_store16(wG,      st + 2*TILE_B + dsto, st + 3*TILE_B + dsto);
    }
    __syncthreads();

    const int NCH = Dv / 32;   // 64
    for (int c = 0; c < NCH; c++) {
        char* nxt = smem + ((c + 1) & 1) * STAGE_B;
        if (c + 1 < NCH) {
            cvt_store16(aG + (c+1)*32, nxt + dsto,            nxt + TILE_B   + dsto);
            cvt_store16(wG + (c+1)*32, nxt + 2*TILE_B + dsto, nxt + 3*TILE_B + dsto);
        }

        const uint32_t cur = smem_u32(smem + (c & 1) * STAGE_B);
        #pragma unroll
        for (int ks = 0; ks < 2; ks++) {
            uint32_t ah[4][4], al[4][4], bh[4][2], bl[4][2];
            #pragma unroll
            for (int mi = 0; mi < 4; mi++) {
                const uint32_t off = (uint32_t)(((wm*64 + mi*16 + la_r)*SA + ks*16 + la_k) * 2);
                ldsm4(cur + off,          ah[mi]);
                ldsm4(cur + TILE_B + off, al[mi]);
            }
            #pragma unroll
            for (int p = 0; p < 2; p++) {
                const uint32_t off = (uint32_t)(((wn*32 + p*16 + lb_c)*SA + ks*16 + lb_k) * 2);
                uint32_t t[4];
                ldsm4(cur + 2*TILE_B + off, t);
                bh[2*p][0] = t[0]; bh[2*p][1] = t[1];
                bh[2*p+1][0] = t[2]; bh[2*p+1][1] = t[3];
                ldsm4(cur + 3*TILE_B + off, t);
                bl[2*p][0] = t[0]; bl[2*p][1] = t[1];
                bl[2*p+1][0] = t[2]; bl[2*p+1][1] = t[3];
            }
            #pragma unroll
            for (int mi = 0; mi < 4; mi++)
                #pragma unroll
                for (int ni = 0; ni < 4; ni++) {
                    mma16816(acc[mi][ni], ah[mi], bh[ni]);
                    mma16816(acc[mi][ni], al[mi], bh[ni]);
                    mma16816(acc[mi][ni], ah[mi], bl[ni]);
                }
        }
        __syncthreads();
    }

    // epilogue: fused RoPE + fp32 store (thread holds (row, col even-pair))
    #pragma unroll
    for (int mi = 0; mi < 4; mi++) {
        const int gr0 = row0 + wm*64 + mi*16 + (lane >> 2);
        const int gr1 = gr0 + 8;
        #pragma unroll
        for (int ni = 0; ni < 4; ni++) {
            const int gc = col0 + wn*32 + ni*8 + (lane & 3)*2;
            float c0 = acc[mi][ni][0], c1 = acc[mi][ni][1];
            float c2 = acc[mi][ni][2], c3 = acc[mi][ni][3];
            if (ROPE) {
                const int ip = (gc & (DKv - 1)) >> 1;
                const int s0 = gr0 & (Sv - 1), s1 = gr1 & (Sv - 1);
                float ca = fc[s0*64 + ip], sa = fs[s0*64 + ip];
                float cb = fc[s1*64 + ip], sb = fs[s1*64 + ip];
                float t0 = c0*ca - c1*sa, t1 = c0*sa + c1*ca;
                float t2 = c2*cb - c3*sb, t3 = c2*sb + c3*cb;
                c0 = t0; c1 = t1; c2 = t2; c3 = t3;
            }
            float2 r0; r0.x = c0; r0.y = c1;
            float2 r1; r1.x = c2; r1.y = c3;
            *(float2*)(C + (size_t)gr0 * Dv + gc) = r0;
            *(float2*)(C + (size_t)gr1 * Dv + gc) = r1;
        }
    }
}

// ---------------------------------------------------------------------------
// Flash attention, fp32, online softmax, strict causal (unchanged from R1).
// ---------------------------------------------------------------------------
__global__ __launch_bounds__(256)
void attn_kernel(const float* __restrict__ Q, const float* __restrict__ Kp,
                 const float* __restrict__ Vp, float* __restrict__ ctx)
{
    extern __shared__ float sm[];
    float* Qs = sm;                   // [64][129]
    float* Ks = Qs + 64*129;          // [64][129]
    float* Vs = Ks + 64*129;          // [64][128]
    float* Ps = Vs + 64*128;          // [64][65]

    const int tid = threadIdx.x;
    const int tx  = tid & 15;
    const int ty  = tid >> 4;
    const int q0  = blockIdx.x * 64;
    const int h   = blockIdx.y;
    const int b   = blockIdx.z;
    const size_t hoff = (size_t)h * DKv;

    {
        const int r  = tid >> 2;
        const int c0 = (tid & 3) * 32;
        const float* src = Q + ((size_t)(b*Sv + q0 + r)) * Dv + hoff + c0;
        #pragma unroll
        for (int u = 0; u < 8; u++) {
            float4 v = *(const float4*)(src + u*4);
            Qs[r*129 + c0 + u*4 + 0] = v.x;
            Qs[r*129 + c0 + u*4 + 1] = v.y;
            Qs[r*129 + c0 + u*4 + 2] = v.z;
            Qs[r*129 + c0 + u*4 + 3] = v.w;
        }
    }

    float m_run[4], l_run[4], acc[4][8];
    #pragma unroll
    for (int i = 0; i < 4; i++) {
        m_run[i] = -1e30f; l_run[i] = 0.0f;
        #pragma unroll
        for (int j = 0; j < 8; j++) acc[i][j] = 0.0f;
    }

    const int r0 = ty * 4;
    const float scale = 0.08838834764831845f;
    const int n_kt = (q0 >> 6) + 1;

    for (int kt = 0; kt < n_kt; kt++) {
        const int k0 = kt * 64;
        __syncthreads();
        {
            const int r  = tid >> 2;
            const int c0 = (tid & 3) * 32;
            const float* ksrc = Kp + ((size_t)(b*Sv + k0 + r)) * Dv + hoff + c0;
            const float* vsrc = Vp + ((size_t)(b*Sv + k0 + r)) * Dv + hoff + c0;
            #pragma unroll
            for (int u = 0; u < 8; u++) {
                float4 kv = *(const float4*)(ksrc + u*4);
                Ks[r*129 + c0 + u*4 + 0] = kv.x;
                Ks[r*129 + c0 + u*4 + 1] = kv.y;
                Ks[r*129 + c0 + u*4 + 2] = kv.z;
                Ks[r*129 + c0 + u*4 + 3] = kv.w;
                float4 vv = *(const float4*)(vsrc + u*4);
                *(float4*)(Vs + r*128 + c0 + u*4) = vv;
            }
        }
        __syncthreads();

        float sc[4][4];
        #pragma unroll
        for (int i = 0; i < 4; i++)
            #pragma unroll
            for (int j = 0; j < 4; j++) sc[i][j] = 0.0f;

        #pragma unroll 8
        for (int k = 0; k < 128; k++) {
            float a[4], bq[4];
            #pragma unroll
            for (int i = 0; i < 4; i++) a[i]  = Qs[(r0 + i)*129 + k];
            #pragma unroll
            for (int j = 0; j < 4; j++) bq[j] = Ks[(tx*4 + j)*129 + k];
            #pragma unroll
            for (int i = 0; i < 4; i++)
                #pragma unroll
                for (int j = 0; j < 4; j++) sc[i][j] = fmaf(a[i], bq[j], sc[i][j]);
        }

        float tm[4];
        #pragma unroll
        for (int i = 0; i < 4; i++) {
            const int gq = q0 + r0 + i;
            #pragma unroll
            for (int j = 0; j < 4; j++) {
                sc[i][j] *= scale;
                if (k0 + tx*4 + j > gq) sc[i][j] = -1e30f;
            }
            tm[i] = fmaxf(fmaxf(sc[i][0], sc[i][1]), fmaxf(sc[i][2], sc[i][3]));
        }
        #pragma unroll
        for (int i = 0; i < 4; i++) {
            #pragma unroll
            for (int off = 8; off > 0; off >>= 1)
                tm[i] = fmaxf(tm[i], __shfl_xor_sync(0xffffffffu, tm[i], off, 16));
        }

        float alpha[4], ts[4];
        #pragma unroll
        for (int i = 0; i < 4; i++) {
            float mn = fmaxf(m_run[i], tm[i]);
            alpha[i] = __expf(m_run[i] - mn);
            m_run[i] = mn;
            float s = 0.0f;
            #pragma unroll
            for (int j = 0; j < 4; j++) {
                sc[i][j] = __expf(sc[i][j] - mn);
                s += sc[i][j];
            }
            ts[i] = s;
        }
        #pragma unroll
        for (int i = 0; i < 4; i++) {
            #pragma unroll
            for (int off = 8; off > 0; off >>= 1)
                ts[i] += __shfl_xor_sync(0xffffffffu, ts[i], off, 16);
            l_run[i] = l_run[i] * alpha[i] + ts[i];
        }

        #pragma unroll
        for (int i = 0; i < 4; i++)
            #pragma unroll
            for (int j = 0; j < 4; j++)
                Ps[(r0 + i)*65 + tx*4 + j] = sc[i][j];
        __syncthreads();

        #pragma unroll
        for (int i = 0; i < 4; i++)
            #pragma unroll
            for (int j = 0; j < 8; j++) acc[i][j] *= alpha[i];

        #pragma unroll 4
        for (int jj = 0; jj < 64; jj++) {
            float p[4];
            #pragma unroll
            for (int i = 0; i < 4; i++) p[i] = Ps[(r0 + i)*65 + jj];
            float4 v0 = *(const float4*)(Vs + jj*128 + tx*4);
            float4 v1 = *(const float4*)(Vs + jj*128 + 64 + tx*4);
            #pragma unroll
            for (int i = 0; i < 4; i++) {
                acc[i][0] = fmaf(p[i], v0.x, acc[i][0]);
                acc[i][1] = fmaf(p[i], v0.y, acc[i][1]);
                acc[i][2] = fmaf(p[i], v0.z, acc[i][2]);
                acc[i][3] = fmaf(p[i], v0.w, acc[i][3]);
                acc[i][4] = fmaf(p[i], v1.x, acc[i][4]);
                acc[i][5] = fmaf(p[i], v1.y, acc[i][5]);
                acc[i][6] = fmaf(p[i], v1.z, acc[i][6]);
                acc[i][7] = fmaf(p[i], v1.w, acc[i][7]);
            }
        }
    }

    #pragma unroll
    for (int i = 0; i < 4; i++) {
        const float inv = 1.0f / l_run[i];
        const int gq = q0 + r0 + i;
        float* dst = ctx + ((size_t)(b*Sv + gq)) * Dv + hoff;
        float4 o0; o0.x = acc[i][0]*inv; o0.y = acc[i][1]*inv;
                   o0.z = acc[i][2]*inv; o0.w = acc[i][3]*inv;
        float4 o1; o1.x = acc[i][4]*inv; o1.y = acc[i][5]*inv;
                   o1.z = acc[i][6]*inv; o1.w = acc[i][7]*inv;
        *(float4*)(dst + tx*4)      = o0;
        *(float4*)(dst + 64 + tx*4) = o1;
    }
}

// ---------------------------------------------------------------------------
extern "C" void kernel_launch(void* const* d_in, const int* in_sizes, int n_in,
                              void* d_out, int out_size)
{
    const float* x  = (const float*)d_in[0];
    const float* fc = (const float*)d_in[1];
    const float* fs = (const float*)d_in[2];
    // d_in[3] = mask (unused: -1e9 mask == strict causal in f32)
    const float* Wq = (const float*)d_in[4];
    const float* Wk = (const float*)d_in[5];
    const float* Wv = (const float*)d_in[6];
    const float* Wo = (const float*)d_in[7];

    float* out  = (float*)d_out;
    float* outK = out  + (size_t)Mv*Dv;
    float* outV = outK + (size_t)Mv*Dv;

    float *Qbuf, *Cbuf;
    cudaGetSymbolAddress((void**)&Qbuf, g_Q);
    cudaGetSymbolAddress((void**)&Cbuf, g_ctx);

    cudaFuncSetAttribute(gemm_mma<true >, cudaFuncAttributeMaxDynamicSharedMemorySize, GSM_TOTAL);
    cudaFuncSetAttribute(gemm_mma<false>, cudaFuncAttributeMaxDynamicSharedMemorySize, GSM_TOTAL);

    dim3 ggrid(Dv/128, Mv/128);   // (16, 32)
    gemm_mma<true ><<<ggrid, 256, GSM_TOTAL>>>(x, Wq, fc, fs, Qbuf);
    gemm_mma<true ><<<ggrid, 256, GSM_TOTAL>>>(x, Wk, fc, fs, outK);
    gemm_mma<false><<<ggrid, 256, GSM_TOTAL>>>(x, Wv, fc, fs, outV);

    const int smem = (64*129*2 + 64*128 + 64*65) * (int)sizeof(float);  // 115456 B
    cudaFuncSetAttribute(attn_kernel, cudaFuncAttributeMaxDynamicSharedMemorySize, smem);
    attn_kernel<<<dim3(Sv/64, Hv, Bv), 256, smem>>>(Qbuf, outK, outV, Cbuf);

    gemm_mma<false><<<ggrid, 256, GSM_TOTAL>>>(Cbuf, Wo, fc, fs, out);
}

// round 7
// speedup vs baseline: 2.1003x; 1.3093x over previous
#include <cuda_runtime.h>
#include <cuda_bf16.h>
#include <math.h>
#include <stdint.h>

#define Bv  2
#define Sv  2048
#define Dv  2048
#define Hv  16
#define DKv 128
#define Mv  (Bv*Sv)   // 4096

// Scratch (allocation-free rule: __device__ globals)
__device__ float g_Q[(size_t)Mv*Dv];    // 32MB: post-RoPE Q
__device__ float g_ctx[(size_t)Mv*Dv];  // 32MB: attention context

// ---------------------------------------------------------------------------
// helpers
// ---------------------------------------------------------------------------
__device__ __forceinline__ uint32_t smem_u32(const void* p){
    uint32_t a;
    asm("{ .reg .u64 t; cvta.to.shared.u64 t, %1; cvt.u32.u64 %0, t; }" : "=r"(a) : "l"(p));
    return a;
}
__device__ __forceinline__ uint32_t pack_bf2(float x, float y){
    __nv_bfloat162 h = __floats2bfloat162_rn(x, y);
    return *reinterpret_cast<uint32_t*>(&h);
}
__device__ __forceinline__ void ldsm4(uint32_t addr, uint32_t r[4]){
    asm volatile("ldmatrix.sync.aligned.m8n8.x4.shared.b16 {%0,%1,%2,%3}, [%4];"
                 : "=r"(r[0]), "=r"(r[1]), "=r"(r[2]), "=r"(r[3]) : "r"(addr));
}
__device__ __forceinline__ void ldsm4t(uint32_t addr, uint32_t r[4]){
    asm volatile("ldmatrix.sync.aligned.m8n8.x4.trans.shared.b16 {%0,%1,%2,%3}, [%4];"
                 : "=r"(r[0]), "=r"(r[1]), "=r"(r[2]), "=r"(r[3]) : "r"(addr));
}
__device__ __forceinline__ void mma16816(float c[4], const uint32_t a[4], const uint32_t b[2]){
    asm volatile(
        "mma.sync.aligned.m16n8k16.row.col.f32.bf16.bf16.f32 "
        "{%0,%1,%2,%3}, {%4,%5,%6,%7}, {%8,%9}, {%0,%1,%2,%3};"
        : "+f"(c[0]), "+f"(c[1]), "+f"(c[2]), "+f"(c[3])
        : "r"(a[0]), "r"(a[1]), "r"(a[2]), "r"(a[3]), "r"(b[0]), "r"(b[1]));
}
__device__ __forceinline__ void split2(float x, float y, uint32_t& hi, uint32_t& lo){
    float hx = __bfloat162float(__float2bfloat16(x));
    float hy = __bfloat162float(__float2bfloat16(y));
    hi = pack_bf2(hx, hy);
    lo = pack_bf2(x - hx, y - hy);
}

// Convert 16 fp32 (scaled) -> 16 bf16 hi + lo, store as 2x uint4 each.
__device__ __forceinline__ void cvt_split16(const float* __restrict__ src, float scale,
                                            char* dhi, char* dlo)
{
    uint32_t h[8], l[8];
    #pragma unroll
    for (int u = 0; u < 4; u++) {
        float4 v = ((const float4*)src)[u];
        v.x *= scale; v.y *= scale; v.z *= scale; v.w *= scale;
        split2(v.x, v.y, h[2*u],   l[2*u]);
        split2(v.z, v.w, h[2*u+1], l[2*u+1]);
    }
    ((uint4*)dhi)[0] = make_uint4(h[0], h[1], h[2], h[3]);
    ((uint4*)dhi)[1] = make_uint4(h[4], h[5], h[6], h[7]);
    ((uint4*)dlo)[0] = make_uint4(l[0], l[1], l[2], l[3]);
    ((uint4*)dlo)[1] = make_uint4(l[4], l[5], l[6], l[7]);
}

// ---------------------------------------------------------------------------
// bf16 mma.sync GEMM with hi/lo split: C[M,N] = A[M,K] * W[N,K]^T (fp32 I/O)
// 128x128 tile, BK=32, 256 threads (8 warps, 2x4), fused RoPE epilogue.
// ---------------------------------------------------------------------------
#define SA      40
#define TILE_B  (128*SA*2)      // 10240 B per matrix tile
#define STAGE_B (4*TILE_B)      // 40960 B
#define GSM_TOTAL (2*STAGE_B)   // 81920 B

template<bool ROPE>
__global__ __launch_bounds__(256, 1)
void gemm_mma(const float* __restrict__ A, const float* __restrict__ W,
              const float* __restrict__ fc, const float* __restrict__ fs,
              float* __restrict__ C)
{
    extern __shared__ __align__(1024) char smem[];
    const int tid  = threadIdx.x;
    const int lane = tid & 31;
    const int wid  = tid >> 5;
    const int wm   = wid >> 2;
    const int wn   = wid & 3;
    const int row0 = blockIdx.y * 128;
    const int col0 = blockIdx.x * 128;

    float acc[4][4][4];
    #pragma unroll
    for (int i = 0; i < 4; i++)
        #pragma unroll
        for (int j = 0; j < 4; j++)
            #pragma unroll
            for (int q = 0; q < 4; q++) acc[i][j][q] = 0.0f;

    const int la_r = (lane & 7) + ((lane >> 3) & 1) * 8;
    const int la_k = (lane >> 4) * 8;
    const int lb_c = (lane & 7) + (lane >> 4) * 8;
    const int lb_k = ((lane >> 3) & 1) * 8;

    const int grow = tid >> 1;
    const int half = tid & 1;
    const float* aG = A + (size_t)(row0 + grow) * Dv + half * 16;
    const float* wG = W + (size_t)(col0 + grow) * Dv + half * 16;
    const int dsto = grow * (SA*2) + half * 32;

    {
        char* st = smem;
        cvt_split16(aG, 1.0f, st + dsto,            st + TILE_B   + dsto);
        cvt_split16(wG, 1.0f, st + 2*TILE_B + dsto, st + 3*TILE_B + dsto);
    }
    __syncthreads();

    const int NCH = Dv / 32;   // 64
    for (int c = 0; c < NCH; c++) {
        char* nxt = smem + ((c + 1) & 1) * STAGE_B;
        if (c + 1 < NCH) {
            cvt_split16(aG + (c+1)*32, 1.0f, nxt + dsto,            nxt + TILE_B   + dsto);
            cvt_split16(wG + (c+1)*32, 1.0f, nxt + 2*TILE_B + dsto, nxt + 3*TILE_B + dsto);
        }

        const uint32_t cur = smem_u32(smem + (c & 1) * STAGE_B);
        #pragma unroll
        for (int ks = 0; ks < 2; ks++) {
            uint32_t ah[4][4], al[4][4], bh[4][2], bl[4][2];
            #pragma unroll
            for (int mi = 0; mi < 4; mi++) {
                const uint32_t off = (uint32_t)(((wm*64 + mi*16 + la_r)*SA + ks*16 + la_k) * 2);
                ldsm4(cur + off,          ah[mi]);
                ldsm4(cur + TILE_B + off, al[mi]);
            }
            #pragma unroll
            for (int p = 0; p < 2; p++) {
                const uint32_t off = (uint32_t)(((wn*32 + p*16 + lb_c)*SA + ks*16 + lb_k) * 2);
                uint32_t t[4];
                ldsm4(cur + 2*TILE_B + off, t);
                bh[2*p][0] = t[0]; bh[2*p][1] = t[1];
                bh[2*p+1][0] = t[2]; bh[2*p+1][1] = t[3];
                ldsm4(cur + 3*TILE_B + off, t);
                bl[2*p][0] = t[0]; bl[2*p][1] = t[1];
                bl[2*p+1][0] = t[2]; bl[2*p+1][1] = t[3];
            }
            #pragma unroll
            for (int mi = 0; mi < 4; mi++)
                #pragma unroll
                for (int ni = 0; ni < 4; ni++) {
                    mma16816(acc[mi][ni], ah[mi], bh[ni]);
                    mma16816(acc[mi][ni], al[mi], bh[ni]);
                    mma16816(acc[mi][ni], ah[mi], bl[ni]);
                }
        }
        __syncthreads();
    }

    #pragma unroll
    for (int mi = 0; mi < 4; mi++) {
        const int gr0 = row0 + wm*64 + mi*16 + (lane >> 2);
        const int gr1 = gr0 + 8;
        #pragma unroll
        for (int ni = 0; ni < 4; ni++) {
            const int gc = col0 + wn*32 + ni*8 + (lane & 3)*2;
            float c0 = acc[mi][ni][0], c1 = acc[mi][ni][1];
            float c2 = acc[mi][ni][2], c3 = acc[mi][ni][3];
            if (ROPE) {
                const int ip = (gc & (DKv - 1)) >> 1;
                const int s0 = gr0 & (Sv - 1), s1 = gr1 & (Sv - 1);
                float ca = fc[s0*64 + ip], sa = fs[s0*64 + ip];
                float cb = fc[s1*64 + ip], sb = fs[s1*64 + ip];
                float t0 = c0*ca - c1*sa, t1 = c0*sa + c1*ca;
                float t2 = c2*cb - c3*sb, t3 = c2*sb + c3*cb;
                c0 = t0; c1 = t1; c2 = t2; c3 = t3;
            }
            float2 r0; r0.x = c0; r0.y = c1;
            float2 r1; r1.x = c2; r1.y = c3;
            *(float2*)(C + (size_t)gr0 * Dv + gc) = r0;
            *(float2*)(C + (size_t)gr1 * Dv + gc) = r1;
        }
    }
}

// ---------------------------------------------------------------------------
// Tensor-core flash attention (mma.sync bf16, hi/lo split both GEMMs).
// Block: 64 q-rows of one (b,h); 128 threads = 4 warps x 16 rows.
// Each warp owns the full 64-wide kv tile and full dk=128 -> no cross-warp
// softmax/ctx reductions. P stays in registers (C-frag == A-frag layout).
// SMEM: Qh Ql Kh Kl Vh Vl, each [64][136] bf16 (stride 17x16B: LDSM
// conflict-free, incl. .trans V loads). Total 102KB -> 2 CTAs/SM.
// ---------------------------------------------------------------------------
#define SP      136
#define ATILE   (64*SP*2)        // 17408 B
#define ASM_TOT (6*ATILE)        // 104448 B

__global__ __launch_bounds__(128, 2)
void attn_mma(const float* __restrict__ Q, const float* __restrict__ Kp,
              const float* __restrict__ Vp, float* __restrict__ ctx)
{
    extern __shared__ __align__(16) char smem[];
    const uint32_t sb = smem_u32(smem);
    const int tid  = threadIdx.x;
    const int lane = tid & 31;
    const int warp = tid >> 5;
    const int qt   = blockIdx.x;
    const int q0   = qt * 64;
    const int h    = blockIdx.y;
    const int b    = blockIdx.z;
    const size_t hoff = (size_t)h * DKv;

    const uint32_t QH = 0,        QL = ATILE,   KH = 2*ATILE;
    const uint32_t VH = 4*ATILE;

    // load Q (pre-scaled by 1/sqrt(dk)), split hi/lo
    {
        const float scale = 0.08838834764831845f;
        const int r  = tid >> 1;
        const int c0 = (tid & 1) * 64;
        const float* src = Q + (size_t)(b*Sv + q0 + r) * Dv + hoff + c0;
        #pragma unroll
        for (int u = 0; u < 4; u++) {
            const int d = (r*SP + c0 + u*16) * 2;
            cvt_split16(src + u*16, scale, smem + QH + d, smem + QL + d);
        }
    }

    float ctxa[16][4];
    #pragma unroll
    for (int i = 0; i < 16; i++)
        #pragma unroll
        for (int j = 0; j < 4; j++) ctxa[i][j] = 0.0f;
    float m0 = -1e30f, m1 = -1e30f, l0 = 0.0f, l1 = 0.0f;

    for (int kt = 0; kt <= qt; kt++) {
        __syncthreads();
        {
            const int r  = tid >> 1;
            const int c0 = (tid & 1) * 64;
            const float* ks = Kp + (size_t)(b*Sv + kt*64 + r) * Dv + hoff + c0;
            const float* vs = Vp + (size_t)(b*Sv + kt*64 + r) * Dv + hoff + c0;
            #pragma unroll
            for (int u = 0; u < 4; u++) {
                const int d = (r*SP + c0 + u*16) * 2;
                cvt_split16(ks + u*16, 1.0f, smem + KH + d,       smem + KH + ATILE + d);
                cvt_split16(vs + u*16, 1.0f, smem + VH + d,       smem + VH + ATILE + d);
            }
        }
        __syncthreads();

        // ---- scores: S[16 x 64] per warp over dk=128, hi/lo 3-term ----
        float sc[8][4];
        #pragma unroll
        for (int nt = 0; nt < 8; nt++)
            #pragma unroll
            for (int j = 0; j < 4; j++) sc[nt][j] = 0.0f;

        #pragma unroll
        for (int ks = 0; ks < 8; ks++) {
            uint32_t qh[4], ql[4];
            const uint32_t qaddr = sb + QH +
                (uint32_t)(((warp*16 + (lane & 15))*SP + ks*16 + (lane >> 4)*8) * 2);
            ldsm4(qaddr,         qh);
            ldsm4(qaddr + ATILE, ql);
            #pragma unroll
            for (int p = 0; p < 4; p++) {
                const uint32_t kaddr = sb + KH +
                    (uint32_t)(((p*16 + (lane & 15))*SP + ks*16 + (lane >> 4)*8) * 2);
                uint32_t th[4], tl[4];
                ldsm4(kaddr,         th);
                ldsm4(kaddr + ATILE, tl);
                uint32_t bh0[2] = {th[0], th[2]}, bh1[2] = {th[1], th[3]};
                uint32_t bl0[2] = {tl[0], tl[2]}, bl1[2] = {tl[1], tl[3]};
                mma16816(sc[2*p],   qh, bh0);
                mma16816(sc[2*p],   ql, bh0);
                mma16816(sc[2*p],   qh, bl0);
                mma16816(sc[2*p+1], qh, bh1);
                mma16816(sc[2*p+1], ql, bh1);
                mma16816(sc[2*p+1], qh, bl1);
            }
        }

        // ---- softmax (rows: lane>>2 and +8; cols: nt*8 + (lane&3)*2) ----
        const int gr0 = q0 + warp*16 + (lane >> 2);
        const int gr1 = gr0 + 8;
        if (kt == qt) {
            #pragma unroll
            for (int nt = 0; nt < 8; nt++) {
                const int cb = kt*64 + nt*8 + (lane & 3)*2;
                if (cb     > gr0) sc[nt][0] = -1e30f;
                if (cb + 1 > gr0) sc[nt][1] = -1e30f;
                if (cb     > gr1) sc[nt][2] = -1e30f;
                if (cb + 1 > gr1) sc[nt][3] = -1e30f;
            }
        }
        float mx0 = -1e30f, mx1 = -1e30f;
        #pragma unroll
        for (int nt = 0; nt < 8; nt++) {
            mx0 = fmaxf(mx0, fmaxf(sc[nt][0], sc[nt][1]));
            mx1 = fmaxf(mx1, fmaxf(sc[nt][2], sc[nt][3]));
        }
        mx0 = fmaxf(mx0, __shfl_xor_sync(0xffffffffu, mx0, 1));
        mx0 = fmaxf(mx0, __shfl_xor_sync(0xffffffffu, mx0, 2));
        mx1 = fmaxf(mx1, __shfl_xor_sync(0xffffffffu, mx1, 1));
        mx1 = fmaxf(mx1, __shfl_xor_sync(0xffffffffu, mx1, 2));

        const float mn0 = fmaxf(m0, mx0), mn1 = fmaxf(m1, mx1);
        const float a0 = __expf(m0 - mn0), a1 = __expf(m1 - mn1);
        m0 = mn0; m1 = mn1;

        float s0 = 0.0f, s1 = 0.0f;
        #pragma unroll
        for (int nt = 0; nt < 8; nt++) {
            sc[nt][0] = __expf(sc[nt][0] - mn0);
            sc[nt][1] = __expf(sc[nt][1] - mn0);
            sc[nt][2] = __expf(sc[nt][2] - mn1);
            sc[nt][3] = __expf(sc[nt][3] - mn1);
            s0 += sc[nt][0] + sc[nt][1];
            s1 += sc[nt][2] + sc[nt][3];
        }
        s0 += __shfl_xor_sync(0xffffffffu, s0, 1);
        s0 += __shfl_xor_sync(0xffffffffu, s0, 2);
        s1 += __shfl_xor_sync(0xffffffffu, s1, 1);
        s1 += __shfl_xor_sync(0xffffffffu, s1, 2);
        l0 = l0 * a0 + s0;
        l1 = l1 * a1 + s1;

        #pragma unroll
        for (int nt = 0; nt < 16; nt++) {
            ctxa[nt][0] *= a0; ctxa[nt][1] *= a0;
            ctxa[nt][2] *= a1; ctxa[nt][3] *= a1;
        }

        // ---- pack P (C-frag -> A-frag), hi/lo ----
        uint32_t pah[4][4], pal[4][4];
        #pragma unroll
        for (int k2 = 0; k2 < 4; k2++) {
            split2(sc[2*k2][0],   sc[2*k2][1],   pah[k2][0], pal[k2][0]);
            split2(sc[2*k2][2],   sc[2*k2][3],   pah[k2][1], pal[k2][1]);
            split2(sc[2*k2+1][0], sc[2*k2+1][1], pah[k2][2], pal[k2][2]);
            split2(sc[2*k2+1][2], sc[2*k2+1][3], pah[k2][3], pal[k2][3]);
        }

        // ---- ctx += P @ V  (V via ldmatrix.trans) ----
        #pragma unroll
        for (int k2 = 0; k2 < 4; k2++) {
            #pragma unroll
            for (int p = 0; p < 8; p++) {
                const uint32_t vaddr = sb + VH +
                    (uint32_t)(((k2*16 + (lane & 15))*SP + p*16 + (lane >> 4)*8) * 2);
                uint32_t vh[4], vl[4];
                ldsm4t(vaddr,         vh);
                ldsm4t(vaddr + ATILE, vl);
                uint32_t bh0[2] = {vh[0], vh[1]}, bh1[2] = {vh[2], vh[3]};
                uint32_t bl0[2] = {vl[0], vl[1]}, bl1[2] = {vl[2], vl[3]};
                mma16816(ctxa[2*p],   pah[k2], bh0);
                mma16816(ctxa[2*p],   pal[k2], bh0);
                mma16816(ctxa[2*p],   pah[k2], bl0);
                mma16816(ctxa[2*p+1], pah[k2], bh1);
                mma16816(ctxa[2*p+1], pal[k2], bh1);
                mma16816(ctxa[2*p+1], pah[k2], bl1);
            }
        }
    }

    // ---- epilogue: ctx / l ----
    const float i0 = 1.0f / l0, i1 = 1.0f / l1;
    const int r0g = b*Sv + q0 + warp*16 + (lane >> 2);
    const int r1g = r0g + 8;
    #pragma unroll
    for (int nt = 0; nt < 16; nt++) {
        const size_t col = hoff + nt*8 + (lane & 3)*2;
        float2 o0; o0.x = ctxa[nt][0]*i0; o0.y = ctxa[nt][1]*i0;
        float2 o1; o1.x = ctxa[nt][2]*i1; o1.y = ctxa[nt][3]*i1;
        *(float2*)(ctx + (size_t)r0g * Dv + col) = o0;
        *(float2*)(ctx + (size_t)r1g * Dv + col) = o1;
    }
}

// ---------------------------------------------------------------------------
extern "C" void kernel_launch(void* const* d_in, const int* in_sizes, int n_in,
                              void* d_out, int out_size)
{
    const float* x  = (const float*)d_in[0];
    const float* fc = (const float*)d_in[1];
    const float* fs = (const float*)d_in[2];
    // d_in[3] = mask (unused: -1e9 mask == strict causal in f32)
    const float* Wq = (const float*)d_in[4];
    const float* Wk = (const float*)d_in[5];
    const float* Wv = (const float*)d_in[6];
    const float* Wo = (const float*)d_in[7];

    float* out  = (float*)d_out;
    float* outK = out  + (size_t)Mv*Dv;
    float* outV = outK + (size_t)Mv*Dv;

    float *Qbuf, *Cbuf;
    cudaGetSymbolAddress((void**)&Qbuf, g_Q);
    cudaGetSymbolAddress((void**)&Cbuf, g_ctx);

    cudaFuncSetAttribute(gemm_mma<true >, cudaFuncAttributeMaxDynamicSharedMemorySize, GSM_TOTAL);
    cudaFuncSetAttribute(gemm_mma<false>, cudaFuncAttributeMaxDynamicSharedMemorySize, GSM_TOTAL);
    cudaFuncSetAttribute(attn_mma,        cudaFuncAttributeMaxDynamicSharedMemorySize, ASM_TOT);

    dim3 ggrid(Dv/128, Mv/128);   // (16, 32)
    gemm_mma<true ><<<ggrid, 256, GSM_TOTAL>>>(x, Wq, fc, fs, Qbuf);
    gemm_mma<true ><<<ggrid, 256, GSM_TOTAL>>>(x, Wk, fc, fs, outK);
    gemm_mma<false><<<ggrid, 256, GSM_TOTAL>>>(x, Wv, fc, fs, outV);

    attn_mma<<<dim3(Sv/64, Hv, Bv), 128, ASM_TOT>>>(Qbuf, outK, outV, Cbuf);

    gemm_mma<false><<<ggrid, 256, GSM_TOTAL>>>(Cbuf, Wo, fc, fs, out);
}

// round 8
// speedup vs baseline: 2.7561x; 1.3123x over previous
#include <cuda_runtime.h>
#include <cuda_bf16.h>
#include <math.h>
#include <stdint.h>

#define Bv  2
#define Sv  2048
#define Dv  2048
#define Hv  16
#define DKv 128
#define Mv  (Bv*Sv)   // 4096

// Scratch (allocation-free rule: __device__ globals)
__device__ float g_Q[(size_t)Mv*Dv];                       // 32MB fp32 post-RoPE Q
__device__ __nv_bfloat16 g_xh[(size_t)Mv*Dv];              // x hi
__device__ __nv_bfloat16 g_xl[(size_t)Mv*Dv];              // x lo
__device__ __nv_bfloat16 g_wh[(size_t)4*Dv*Dv];            // Wq|Wk|Wv|Wo hi
__device__ __nv_bfloat16 g_wl[(size_t)4*Dv*Dv];            // Wq|Wk|Wv|Wo lo
__device__ __nv_bfloat16 g_ch[(size_t)Mv*Dv];              // ctx hi
__device__ __nv_bfloat16 g_cl[(size_t)Mv*Dv];              // ctx lo

// ---------------------------------------------------------------------------
// helpers
// ---------------------------------------------------------------------------
__device__ __forceinline__ uint32_t smem_u32(const void* p){
    uint32_t a;
    asm("{ .reg .u64 t; cvta.to.shared.u64 t, %1; cvt.u32.u64 %0, t; }" : "=r"(a) : "l"(p));
    return a;
}
__device__ __forceinline__ uint32_t pack_bf2(float x, float y){
    __nv_bfloat162 h = __floats2bfloat162_rn(x, y);
    return *reinterpret_cast<uint32_t*>(&h);
}
__device__ __forceinline__ void ldsm4(uint32_t addr, uint32_t r[4]){
    asm volatile("ldmatrix.sync.aligned.m8n8.x4.shared.b16 {%0,%1,%2,%3}, [%4];"
                 : "=r"(r[0]), "=r"(r[1]), "=r"(r[2]), "=r"(r[3]) : "r"(addr));
}
__device__ __forceinline__ void ldsm4t(uint32_t addr, uint32_t r[4]){
    asm volatile("ldmatrix.sync.aligned.m8n8.x4.trans.shared.b16 {%0,%1,%2,%3}, [%4];"
                 : "=r"(r[0]), "=r"(r[1]), "=r"(r[2]), "=r"(r[3]) : "r"(addr));
}
__device__ __forceinline__ void mma16816(float c[4], const uint32_t a[4], const uint32_t b[2]){
    asm volatile(
        "mma.sync.aligned.m16n8k16.row.col.f32.bf16.bf16.f32 "
        "{%0,%1,%2,%3}, {%4,%5,%6,%7}, {%8,%9}, {%0,%1,%2,%3};"
        : "+f"(c[0]), "+f"(c[1]), "+f"(c[2]), "+f"(c[3])
        : "r"(a[0]), "r"(a[1]), "r"(a[2]), "r"(a[3]), "r"(b[0]), "r"(b[1]));
}
__device__ __forceinline__ void split2(float x, float y, uint32_t& hi, uint32_t& lo){
    float hx = __bfloat162float(__float2bfloat16(x));
    float hy = __bfloat162float(__float2bfloat16(y));
    hi = pack_bf2(hx, hy);
    lo = pack_bf2(x - hx, y - hy);
}
__device__ __forceinline__ void cp16(uint32_t dst, const void* src){
    asm volatile("cp.async.cg.shared.global [%0], [%1], 16;" :: "r"(dst), "l"(src));
}
__device__ __forceinline__ void cp_commit(){
    asm volatile("cp.async.commit_group;" ::: "memory");
}
template<int N>
__device__ __forceinline__ void cp_wait(){
    asm volatile("cp.async.wait_group %0;" :: "n"(N) : "memory");
}

// Convert 16 fp32 (scaled) -> 16 bf16 hi + lo, store as 2x uint4 each.
__device__ __forceinline__ void cvt_split16(const float* __restrict__ src, float scale,
                                            char* dhi, char* dlo)
{
    uint32_t h[8], l[8];
    #pragma unroll
    for (int u = 0; u < 4; u++) {
        float4 v = ((const float4*)src)[u];
        v.x *= scale; v.y *= scale; v.z *= scale; v.w *= scale;
        split2(v.x, v.y, h[2*u],   l[2*u]);
        split2(v.z, v.w, h[2*u+1], l[2*u+1]);
    }
    ((uint4*)dhi)[0] = make_uint4(h[0], h[1], h[2], h[3]);
    ((uint4*)dhi)[1] = make_uint4(h[4], h[5], h[6], h[7]);
    ((uint4*)dlo)[0] = make_uint4(l[0], l[1], l[2], l[3]);
    ((uint4*)dlo)[1] = make_uint4(l[4], l[5], l[6], l[7]);
}

// ---------------------------------------------------------------------------
// Elementwise fp32 -> bf16 hi/lo planes (8 elems/thread)
// ---------------------------------------------------------------------------
__global__ __launch_bounds__(256)
void split_k(const float* __restrict__ src, __nv_bfloat16* __restrict__ hi,
             __nv_bfloat16* __restrict__ lo, int n8)
{
    const int i = blockIdx.x * blockDim.x + threadIdx.x;
    if (i >= n8) return;
    const float4* s = (const float4*)src + 2*(size_t)i;
    float4 v0 = s[0], v1 = s[1];
    uint32_t h[4], l[4];
    split2(v0.x, v0.y, h[0], l[0]); split2(v0.z, v0.w, h[1], l[1]);
    split2(v1.x, v1.y, h[2], l[2]); split2(v1.z, v1.w, h[3], l[3]);
    ((uint4*)hi)[i] = make_uint4(h[0], h[1], h[2], h[3]);
    ((uint4*)lo)[i] = make_uint4(l[0], l[1], l[2], l[3]);
}

// ---------------------------------------------------------------------------
// Pipelined bf16 GEMM on pre-split planes:
// C[M,N] = (Ah+Al)[M,K] * (Bh+Bl)[N,K]^T  (3-term), fp32 out, optional RoPE.
// 128x128 tile, BK=32, 256 threads (8 warps 2x4), 4-stage cp.async pipeline.
// SMEM/stage: Ah Al Bh Bl each [128][40] bf16. 4 stages = 160KB.
// ---------------------------------------------------------------------------
#define SA      40
#define TILE_B  (128*SA*2)      // 10240 B
#define STG_B   (4*TILE_B)      // 40960 B
#define GSM_TOTAL (4*STG_B)     // 163840 B
#define NCH     (Dv/32)         // 64

template<bool ROPE>
__global__ __launch_bounds__(256, 1)
void gemm_bf(const __nv_bfloat16* __restrict__ Ah, const __nv_bfloat16* __restrict__ Al,
             const __nv_bfloat16* __restrict__ Bh, const __nv_bfloat16* __restrict__ Bl,
             const float* __restrict__ fc, const float* __restrict__ fs,
             float* __restrict__ C)
{
    extern __shared__ __align__(1024) char smem[];
    const int tid  = threadIdx.x;
    const int lane = tid & 31;
    const int wid  = tid >> 5;
    const int wm   = wid >> 2;
    const int wn   = wid & 3;
    const int row0 = blockIdx.y * 128;
    const int col0 = blockIdx.x * 128;

    float acc[4][4][4];
    #pragma unroll
    for (int i = 0; i < 4; i++)
        #pragma unroll
        for (int j = 0; j < 4; j++)
            #pragma unroll
            for (int q = 0; q < 4; q++) acc[i][j][q] = 0.0f;

    const int la_r = (lane & 7) + ((lane >> 3) & 1) * 8;
    const int la_k = (lane >> 4) * 8;
    const int lb_c = (lane & 7) + (lane >> 4) * 8;
    const int lb_k = ((lane >> 3) & 1) * 8;

    // loader addressing: thread -> (row, 32B half of the 64B k-row)
    const int lrow  = tid >> 1;
    const int lhalf = tid & 1;
    const __nv_bfloat16* aHg = Ah + (size_t)(row0 + lrow) * Dv + lhalf*16;
    const __nv_bfloat16* aLg = Al + (size_t)(row0 + lrow) * Dv + lhalf*16;
    const __nv_bfloat16* bHg = Bh + (size_t)(col0 + lrow) * Dv + lhalf*16;
    const __nv_bfloat16* bLg = Bl + (size_t)(col0 + lrow) * Dv + lhalf*16;
    const uint32_t dsto = (uint32_t)(lrow*(SA*2) + lhalf*32);

    const uint32_t sb = smem_u32(smem);

    // prologue: 3 stages in flight
    #pragma unroll
    for (int s = 0; s < 3; s++) {
        const uint32_t dst = sb + s*STG_B + dsto;
        const size_t go = (size_t)s * 32;
        cp16(dst,                aHg + go);  cp16(dst + 16,             aHg + go + 8);
        cp16(dst +   TILE_B,     aLg + go);  cp16(dst +   TILE_B + 16,  aLg + go + 8);
        cp16(dst + 2*TILE_B,     bHg + go);  cp16(dst + 2*TILE_B + 16,  bHg + go + 8);
        cp16(dst + 3*TILE_B,     bLg + go);  cp16(dst + 3*TILE_B + 16,  bLg + go + 8);
        cp_commit();
    }

    for (int c = 0; c < NCH; c++) {
        cp_wait<2>();
        __syncthreads();

        const uint32_t cur = sb + (c & 3) * STG_B;
        #pragma unroll
        for (int ks = 0; ks < 2; ks++) {
            uint32_t ah[4][4], al[4][4], bh[4][2], bl[4][2];
            #pragma unroll
            for (int mi = 0; mi < 4; mi++) {
                const uint32_t off = (uint32_t)(((wm*64 + mi*16 + la_r)*SA + ks*16 + la_k) * 2);
                ldsm4(cur + off,          ah[mi]);
                ldsm4(cur + TILE_B + off, al[mi]);
            }
            #pragma unroll
            for (int p = 0; p < 2; p++) {
                const uint32_t off = (uint32_t)(((wn*32 + p*16 + lb_c)*SA + ks*16 + lb_k) * 2);
                uint32_t t[4];
                ldsm4(cur + 2*TILE_B + off, t);
                bh[2*p][0] = t[0]; bh[2*p][1] = t[1];
                bh[2*p+1][0] = t[2]; bh[2*p+1][1] = t[3];
                ldsm4(cur + 3*TILE_B + off, t);
                bl[2*p][0] = t[0]; bl[2*p][1] = t[1];
                bl[2*p+1][0] = t[2]; bl[2*p+1][1] = t[3];
            }
            #pragma unroll
            for (int mi = 0; mi < 4; mi++)
                #pragma unroll
                for (int ni = 0; ni < 4; ni++) {
                    mma16816(acc[mi][ni], ah[mi], bh[ni]);
                    mma16816(acc[mi][ni], al[mi], bh[ni]);
                    mma16816(acc[mi][ni], ah[mi], bl[ni]);
                }
        }

        // issue chunk c+3 into stage (c+3)&3 (read-complete since last barrier)
        if (c + 3 < NCH) {
            const uint32_t dst = sb + ((c+3) & 3) * STG_B + dsto;
            const size_t go = (size_t)(c+3) * 32;
            cp16(dst,                aHg + go);  cp16(dst + 16,             aHg + go + 8);
            cp16(dst +   TILE_B,     aLg + go);  cp16(dst +   TILE_B + 16,  aLg + go + 8);
            cp16(dst + 2*TILE_B,     bHg + go);  cp16(dst + 2*TILE_B + 16,  bHg + go + 8);
            cp16(dst + 3*TILE_B,     bLg + go);  cp16(dst + 3*TILE_B + 16,  bLg + go + 8);
        }
        cp_commit();   // unconditional: keeps group numbering exact
    }

    // epilogue: fused RoPE + fp32 store
    #pragma unroll
    for (int mi = 0; mi < 4; mi++) {
        const int gr0 = row0 + wm*64 + mi*16 + (lane >> 2);
        const int gr1 = gr0 + 8;
        #pragma unroll
        for (int ni = 0; ni < 4; ni++) {
            const int gc = col0 + wn*32 + ni*8 + (lane & 3)*2;
            float c0 = acc[mi][ni][0], c1 = acc[mi][ni][1];
            float c2 = acc[mi][ni][2], c3 = acc[mi][ni][3];
            if (ROPE) {
                const int ip = (gc & (DKv - 1)) >> 1;
                const int s0 = gr0 & (Sv - 1), s1 = gr1 & (Sv - 1);
                float ca = fc[s0*64 + ip], sa = fs[s0*64 + ip];
                float cb = fc[s1*64 + ip], sb2 = fs[s1*64 + ip];
                float t0 = c0*ca - c1*sa, t1 = c0*sa + c1*ca;
                float t2 = c2*cb - c3*sb2, t3 = c2*sb2 + c3*cb;
                c0 = t0; c1 = t1; c2 = t2; c3 = t3;
            }
            float2 r0; r0.x = c0; r0.y = c1;
            float2 r1; r1.x = c2; r1.y = c3;
            *(float2*)(C + (size_t)gr0 * Dv + gc) = r0;
            *(float2*)(C + (size_t)gr1 * Dv + gc) = r1;
        }
    }
}

// ---------------------------------------------------------------------------
// Tensor-core flash attention (unchanged dataflow; epilogue now emits
// ctx as bf16 hi/lo planes for the Wo GEMM).
// ---------------------------------------------------------------------------
#define SP      136
#define ATILE   (64*SP*2)        // 17408 B
#define ASM_TOT (6*ATILE)        // 104448 B

__global__ __launch_bounds__(128, 2)
void attn_mma(const float* __restrict__ Q, const float* __restrict__ Kp,
              const float* __restrict__ Vp,
              __nv_bfloat16* __restrict__ ch, __nv_bfloat16* __restrict__ cl)
{
    extern __shared__ __align__(16) char smem[];
    const uint32_t sb = smem_u32(smem);
    const int tid  = threadIdx.x;
    const int lane = tid & 31;
    const int warp = tid >> 5;
    const int qt   = blockIdx.x;
    const int q0   = qt * 64;
    const int h    = blockIdx.y;
    const int b    = blockIdx.z;
    const size_t hoff = (size_t)h * DKv;

    const uint32_t QH = 0, QL = ATILE, KH = 2*ATILE, VH = 4*ATILE;

    {
        const float scale = 0.08838834764831845f;
        const int r  = tid >> 1;
        const int c0 = (tid & 1) * 64;
        const float* src = Q + (size_t)(b*Sv + q0 + r) * Dv + hoff + c0;
        #pragma unroll
        for (int u = 0; u < 4; u++) {
            const int d = (r*SP + c0 + u*16) * 2;
            cvt_split16(src + u*16, scale, smem + QH + d, smem + QL + d);
        }
    }

    float ctxa[16][4];
    #pragma unroll
    for (int i = 0; i < 16; i++)
        #pragma unroll
        for (int j = 0; j < 4; j++) ctxa[i][j] = 0.0f;
    float m0 = -1e30f, m1 = -1e30f, l0 = 0.0f, l1 = 0.0f;

    for (int kt = 0; kt <= qt; kt++) {
        __syncthreads();
        {
            const int r  = tid >> 1;
            const int c0 = (tid & 1) * 64;
            const float* ks = Kp + (size_t)(b*Sv + kt*64 + r) * Dv + hoff + c0;
            const float* vs = Vp + (size_t)(b*Sv + kt*64 + r) * Dv + hoff + c0;
            #pragma unroll
            for (int u = 0; u < 4; u++) {
                const int d = (r*SP + c0 + u*16) * 2;
                cvt_split16(ks + u*16, 1.0f, smem + KH + d, smem + KH + ATILE + d);
                cvt_split16(vs + u*16, 1.0f, smem + VH + d, smem + VH + ATILE + d);
            }
        }
        __syncthreads();

        float sc[8][4];
        #pragma unroll
        for (int nt = 0; nt < 8; nt++)
            #pragma unroll
            for (int j = 0; j < 4; j++) sc[nt][j] = 0.0f;

        #pragma unroll
        for (int ks = 0; ks < 8; ks++) {
            uint32_t qh[4], ql[4];
            const uint32_t qaddr = sb + QH +
                (uint32_t)(((warp*16 + (lane & 15))*SP + ks*16 + (lane >> 4)*8) * 2);
            ldsm4(qaddr,         qh);
            ldsm4(qaddr + ATILE, ql);
            #pragma unroll
            for (int p = 0; p < 4; p++) {
                const uint32_t kaddr = sb + KH +
                    (uint32_t)(((p*16 + (lane & 15))*SP + ks*16 + (lane >> 4)*8) * 2);
                uint32_t th[4], tl[4];
                ldsm4(kaddr,         th);
                ldsm4(kaddr + ATILE, tl);
                uint32_t bh0[2] = {th[0], th[2]}, bh1[2] = {th[1], th[3]};
                uint32_t bl0[2] = {tl[0], tl[2]}, bl1[2] = {tl[1], tl[3]};
                mma16816(sc[2*p],   qh, bh0);
                mma16816(sc[2*p],   ql, bh0);
                mma16816(sc[2*p],   qh, bl0);
                mma16816(sc[2*p+1], qh, bh1);
                mma16816(sc[2*p+1], ql, bh1);
                mma16816(sc[2*p+1], qh, bl1);
            }
        }

        const int gr0 = q0 + warp*16 + (lane >> 2);
        const int gr1 = gr0 + 8;
        if (kt == qt) {
            #pragma unroll
            for (int nt = 0; nt < 8; nt++) {
                const int cb = kt*64 + nt*8 + (lane & 3)*2;
                if (cb     > gr0) sc[nt][0] = -1e30f;
                if (cb + 1 > gr0) sc[nt][1] = -1e30f;
                if (cb     > gr1) sc[nt][2] = -1e30f;
                if (cb + 1 > gr1) sc[nt][3] = -1e30f;
            }
        }
        float mx0 = -1e30f, mx1 = -1e30f;
        #pragma unroll
        for (int nt = 0; nt < 8; nt++) {
            mx0 = fmaxf(mx0, fmaxf(sc[nt][0], sc[nt][1]));
            mx1 = fmaxf(mx1, fmaxf(sc[nt][2], sc[nt][3]));
        }
        mx0 = fmaxf(mx0, __shfl_xor_sync(0xffffffffu, mx0, 1));
        mx0 = fmaxf(mx0, __shfl_xor_sync(0xffffffffu, mx0, 2));
        mx1 = fmaxf(mx1, __shfl_xor_sync(0xffffffffu, mx1, 1));
        mx1 = fmaxf(mx1, __shfl_xor_sync(0xffffffffu, mx1, 2));

        const float mn0 = fmaxf(m0, mx0), mn1 = fmaxf(m1, mx1);
        const float a0 = __expf(m0 - mn0), a1 = __expf(m1 - mn1);
        m0 = mn0; m1 = mn1;

        float s0 = 0.0f, s1 = 0.0f;
        #pragma unroll
        for (int nt = 0; nt < 8; nt++) {
            sc[nt][0] = __expf(sc[nt][0] - mn0);
            sc[nt][1] = __expf(sc[nt][1] - mn0);
            sc[nt][2] = __expf(sc[nt][2] - mn1);
            sc[nt][3] = __expf(sc[nt][3] - mn1);
            s0 += sc[nt][0] + sc[nt][1];
            s1 += sc[nt][2] + sc[nt][3];
        }
        s0 += __shfl_xor_sync(0xffffffffu, s0, 1);
        s0 += __shfl_xor_sync(0xffffffffu, s0, 2);
        s1 += __shfl_xor_sync(0xffffffffu, s1, 1);
        s1 += __shfl_xor_sync(0xffffffffu, s1, 2);
        l0 = l0 * a0 + s0;
        l1 = l1 * a1 + s1;

        #pragma unroll
        for (int nt = 0; nt < 16; nt++) {
            ctxa[nt][0] *= a0; ctxa[nt][1] *= a0;
            ctxa[nt][2] *= a1; ctxa[nt][3] *= a1;
        }

        uint32_t pah[4][4], pal[4][4];
        #pragma unroll
        for (int k2 = 0; k2 < 4; k2++) {
            split2(sc[2*k2][0],   sc[2*k2][1],   pah[k2][0], pal[k2][0]);
            split2(sc[2*k2][2],   sc[2*k2][3],   pah[k2][1], pal[k2][1]);
            split2(sc[2*k2+1][0], sc[2*k2+1][1], pah[k2][2], pal[k2][2]);
            split2(sc[2*k2+1][2], sc[2*k2+1][3], pah[k2][3], pal[k2][3]);
        }

        #pragma unroll
        for (int k2 = 0; k2 < 4; k2++) {
            #pragma unroll
            for (int p = 0; p < 8; p++) {
                const uint32_t vaddr = sb + VH +
                    (uint32_t)(((k2*16 + (lane & 15))*SP + p*16 + (lane >> 4)*8) * 2);
                uint32_t vh[4], vl[4];
                ldsm4t(vaddr,         vh);
                ldsm4t(vaddr + ATILE, vl);
                uint32_t bh0[2] = {vh[0], vh[1]}, bh1[2] = {vh[2], vh[3]};
                uint32_t bl0[2] = {vl[0], vl[1]}, bl1[2] = {vl[2], vl[3]};
                mma16816(ctxa[2*p],   pah[k2], bh0);
                mma16816(ctxa[2*p],   pal[k2], bh0);
                mma16816(ctxa[2*p],   pah[k2], bl0);
                mma16816(ctxa[2*p+1], pah[k2], bh1);
                mma16816(ctxa[2*p+1], pal[k2], bh1);
                mma16816(ctxa[2*p+1], pah[k2], bl1);
            }
        }
    }

    // epilogue: ctx/l -> bf16 hi/lo planes
    const float i0 = 1.0f / l0, i1 = 1.0f / l1;
    const size_t r0g = (size_t)(b*Sv + q0 + warp*16 + (lane >> 2));
    const size_t r1g = r0g + 8;
    #pragma unroll
    for (int nt = 0; nt < 16; nt++) {
        const size_t col = hoff + nt*8 + (lane & 3)*2;
        uint32_t h0, l0u, h1, l1u;
        split2(ctxa[nt][0]*i0, ctxa[nt][1]*i0, h0, l0u);
        split2(ctxa[nt][2]*i1, ctxa[nt][3]*i1, h1, l1u);
        *(uint32_t*)(ch + r0g*Dv + col) = h0;
        *(uint32_t*)(cl + r0g*Dv + col) = l0u;
        *(uint32_t*)(ch + r1g*Dv + col) = h1;
        *(uint32_t*)(cl + r1g*Dv + col) = l1u;
    }
}

// ---------------------------------------------------------------------------
extern "C" void kernel_launch(void* const* d_in, const int* in_sizes, int n_in,
                              void* d_out, int out_size)
{
    const float* x  = (const float*)d_in[0];
    const float* fc = (const float*)d_in[1];
    const float* fs = (const float*)d_in[2];
    // d_in[3] = mask (unused: -1e9 mask == strict causal in f32)
    const float* Wq = (const float*)d_in[4];
    const float* Wk = (const float*)d_in[5];
    const float* Wv = (const float*)d_in[6];
    const float* Wo = (const float*)d_in[7];

    float* out  = (float*)d_out;
    float* outK = out  + (size_t)Mv*Dv;
    float* outV = outK + (size_t)Mv*Dv;

    float *Qbuf;
    __nv_bfloat16 *xh, *xl, *wh, *wl, *ch, *cl;
    cudaGetSymbolAddress((void**)&Qbuf, g_Q);
    cudaGetSymbolAddress((void**)&xh, g_xh);
    cudaGetSymbolAddress((void**)&xl, g_xl);
    cudaGetSymbolAddress((void**)&wh, g_wh);
    cudaGetSymbolAddress((void**)&wl, g_wl);
    cudaGetSymbolAddress((void**)&ch, g_ch);
    cudaGetSymbolAddress((void**)&cl, g_cl);

    cudaFuncSetAttribute(gemm_bf<true >, cudaFuncAttributeMaxDynamicSharedMemorySize, GSM_TOTAL);
    cudaFuncSetAttribute(gemm_bf<false>, cudaFuncAttributeMaxDynamicSharedMemorySize, GSM_TOTAL);
    cudaFuncSetAttribute(attn_mma,       cudaFuncAttributeMaxDynamicSharedMemorySize, ASM_TOT);

    const size_t WN = (size_t)Dv*Dv;     // 4M elems per weight

    // pre-split x and weights into bf16 hi/lo planes
    split_k<<<(Mv*Dv/8 + 255)/256, 256>>>(x,  xh, xl, Mv*Dv/8);
    split_k<<<(WN/8 + 255)/256, 256>>>(Wq, wh,          wl,          (int)(WN/8));
    split_k<<<(WN/8 + 255)/256, 256>>>(Wk, wh + WN,     wl + WN,     (int)(WN/8));
    split_k<<<(WN/8 + 255)/256, 256>>>(Wv, wh + 2*WN,   wl + 2*WN,   (int)(WN/8));
    split_k<<<(WN/8 + 255)/256, 256>>>(Wo, wh + 3*WN,   wl + 3*WN,   (int)(WN/8));

    dim3 ggrid(Dv/128, Mv/128);   // (16, 32)
    gemm_bf<true ><<<ggrid, 256, GSM_TOTAL>>>(xh, xl, wh,        wl,        fc, fs, Qbuf);
    gemm_bf<true ><<<ggrid, 256, GSM_TOTAL>>>(xh, xl, wh + WN,   wl + WN,   fc, fs, outK);
    gemm_bf<false><<<ggrid, 256, GSM_TOTAL>>>(xh, xl, wh + 2*WN, wl + 2*WN, fc, fs, outV);

    attn_mma<<<dim3(Sv/64, Hv, Bv), 128, ASM_TOT>>>(Qbuf, outK, outV, ch, cl);

    gemm_bf<false><<<ggrid, 256, GSM_TOTAL>>>(ch, cl, wh + 3*WN, wl + 3*WN, fc, fs, out);
}

// round 10
// speedup vs baseline: 2.9295x; 1.0629x over previous
#include <cuda_runtime.h>
#include <cuda_bf16.h>
#include <math.h>
#include <stdint.h>

#define Bv  2
#define Sv  2048
#define Dv  2048
#define Hv  16
#define DKv 128
#define Mv  (Bv*Sv)   // 4096

// Scratch (allocation-free rule: __device__ globals)
__device__ __nv_bfloat16 g_xh[(size_t)Mv*Dv];              // x hi
__device__ __nv_bfloat16 g_xl[(size_t)Mv*Dv];              // x lo
__device__ __nv_bfloat16 g_wh[(size_t)4*Dv*Dv];            // Wq|Wk|Wv|Wo hi
__device__ __nv_bfloat16 g_wl[(size_t)4*Dv*Dv];            // Wq|Wk|Wv|Wo lo
__device__ __nv_bfloat16 g_qh[(size_t)Mv*Dv];              // Q (rope, scaled) hi
__device__ __nv_bfloat16 g_ql[(size_t)Mv*Dv];              // Q lo
__device__ __nv_bfloat16 g_kh[(size_t)Mv*Dv];              // K (rope) hi
__device__ __nv_bfloat16 g_kl[(size_t)Mv*Dv];              // K lo
__device__ __nv_bfloat16 g_vh[(size_t)Mv*Dv];              // V hi
__device__ __nv_bfloat16 g_vl[(size_t)Mv*Dv];              // V lo
__device__ __nv_bfloat16 g_ch[(size_t)Mv*Dv];              // ctx hi
__device__ __nv_bfloat16 g_cl[(size_t)Mv*Dv];              // ctx lo

// ---------------------------------------------------------------------------
// helpers
// ---------------------------------------------------------------------------
__device__ __forceinline__ uint32_t smem_u32(const void* p){
    uint32_t a;
    asm("{ .reg .u64 t; cvta.to.shared.u64 t, %1; cvt.u32.u64 %0, t; }" : "=r"(a) : "l"(p));
    return a;
}
__device__ __forceinline__ uint32_t pack_bf2(float x, float y){
    __nv_bfloat162 h = __floats2bfloat162_rn(x, y);
    return *reinterpret_cast<uint32_t*>(&h);
}
__device__ __forceinline__ void ldsm4(uint32_t addr, uint32_t r[4]){
    asm volatile("ldmatrix.sync.aligned.m8n8.x4.shared.b16 {%0,%1,%2,%3}, [%4];"
                 : "=r"(r[0]), "=r"(r[1]), "=r"(r[2]), "=r"(r[3]) : "r"(addr));
}
__device__ __forceinline__ void ldsm4t(uint32_t addr, uint32_t r[4]){
    asm volatile("ldmatrix.sync.aligned.m8n8.x4.trans.shared.b16 {%0,%1,%2,%3}, [%4];"
                 : "=r"(r[0]), "=r"(r[1]), "=r"(r[2]), "=r"(r[3]) : "r"(addr));
}
__device__ __forceinline__ void mma16816(float c[4], const uint32_t a[4], const uint32_t b[2]){
    asm volatile(
        "mma.sync.aligned.m16n8k16.row.col.f32.bf16.bf16.f32 "
        "{%0,%1,%2,%3}, {%4,%5,%6,%7}, {%8,%9}, {%0,%1,%2,%3};"
        : "+f"(c[0]), "+f"(c[1]), "+f"(c[2]), "+f"(c[3])
        : "r"(a[0]), "r"(a[1]), "r"(a[2]), "r"(a[3]), "r"(b[0]), "r"(b[1]));
}
__device__ __forceinline__ void split2(float x, float y, uint32_t& hi, uint32_t& lo){
    float hx = __bfloat162float(__float2bfloat16(x));
    float hy = __bfloat162float(__float2bfloat16(y));
    hi = pack_bf2(hx, hy);
    lo = pack_bf2(x - hx, y - hy);
}
__device__ __forceinline__ void cp16(uint32_t dst, const void* src){
    asm volatile("cp.async.cg.shared.global [%0], [%1], 16;" :: "r"(dst), "l"(src));
}
__device__ __forceinline__ void cp_commit(){
    asm volatile("cp.async.commit_group;" ::: "memory");
}
template<int N>
__device__ __forceinline__ void cp_wait(){
    asm volatile("cp.async.wait_group %0;" :: "n"(N) : "memory");
}

// ---------------------------------------------------------------------------
// Elementwise fp32 -> bf16 hi/lo planes (8 elems/thread)
// ---------------------------------------------------------------------------
__global__ __launch_bounds__(256)
void split_k(const float* __restrict__ src, __nv_bfloat16* __restrict__ hi,
             __nv_bfloat16* __restrict__ lo, int n8)
{
    const int i = blockIdx.x * blockDim.x + threadIdx.x;
    if (i >= n8) return;
    const float4* s = (const float4*)src + 2*(size_t)i;
    float4 v0 = s[0], v1 = s[1];
    uint32_t h[4], l[4];
    split2(v0.x, v0.y, h[0], l[0]); split2(v0.z, v0.w, h[1], l[1]);
    split2(v1.x, v1.y, h[2], l[2]); split2(v1.z, v1.w, h[3], l[3]);
    ((uint4*)hi)[i] = make_uint4(h[0], h[1], h[2], h[3]);
    ((uint4*)lo)[i] = make_uint4(l[0], l[1], l[2], l[3]);
}

// ---------------------------------------------------------------------------
// Pipelined bf16 GEMM on pre-split planes (3-term hi/lo).
// MODE: 0 = fp32 out only (Wo)
//       1 = RoPE + 1/sqrt(dk) scale, hi/lo planes only (Q)
//       2 = RoPE, fp32 out + hi/lo planes (K)
//       3 = fp32 out + hi/lo planes (V)
// 128x128 tile, BK=32, 256 threads (8 warps 2x4), 4-stage cp.async pipeline.
// ---------------------------------------------------------------------------
#define SA      40
#define TILE_B  (128*SA*2)      // 10240 B
#define STG_B   (4*TILE_B)      // 40960 B
#define GSM_TOTAL (4*STG_B)     // 163840 B
#define NCH     (Dv/32)         // 64

template<int MODE>
__global__ __launch_bounds__(256, 1)
void gemm_bf(const __nv_bfloat16* __restrict__ Ah, const __nv_bfloat16* __restrict__ Al,
             const __nv_bfloat16* __restrict__ Bh, const __nv_bfloat16* __restrict__ Bl,
             const float* __restrict__ fc, const float* __restrict__ fs,
             float* __restrict__ C,
             __nv_bfloat16* __restrict__ Ph, __nv_bfloat16* __restrict__ Pl)
{
    extern __shared__ __align__(1024) char smem[];
    const int tid  = threadIdx.x;
    const int lane = tid & 31;
    const int wid  = tid >> 5;
    const int wm   = wid >> 2;
    const int wn   = wid & 3;
    const int row0 = blockIdx.y * 128;
    const int col0 = blockIdx.x * 128;

    float acc[4][4][4];
    #pragma unroll
    for (int i = 0; i < 4; i++)
        #pragma unroll
        for (int j = 0; j < 4; j++)
            #pragma unroll
            for (int q = 0; q < 4; q++) acc[i][j][q] = 0.0f;

    const int la_r = (lane & 7) + ((lane >> 3) & 1) * 8;
    const int la_k = (lane >> 4) * 8;
    const int lb_c = (lane & 7) + (lane >> 4) * 8;
    const int lb_k = ((lane >> 3) & 1) * 8;

    const int lrow  = tid >> 1;
    const int lhalf = tid & 1;
    const __nv_bfloat16* aHg = Ah + (size_t)(row0 + lrow) * Dv + lhalf*16;
    const __nv_bfloat16* aLg = Al + (size_t)(row0 + lrow) * Dv + lhalf*16;
    const __nv_bfloat16* bHg = Bh + (size_t)(col0 + lrow) * Dv + lhalf*16;
    const __nv_bfloat16* bLg = Bl + (size_t)(col0 + lrow) * Dv + lhalf*16;
    const uint32_t dsto = (uint32_t)(lrow*(SA*2) + lhalf*32);

    const uint32_t sb = smem_u32(smem);

    #pragma unroll
    for (int s = 0; s < 3; s++) {
        const uint32_t dst = sb + s*STG_B + dsto;
        const size_t go = (size_t)s * 32;
        cp16(dst,                aHg + go);  cp16(dst + 16,             aHg + go + 8);
        cp16(dst +   TILE_B,     aLg + go);  cp16(dst +   TILE_B + 16,  aLg + go + 8);
        cp16(dst + 2*TILE_B,     bHg + go);  cp16(dst + 2*TILE_B + 16,  bHg + go + 8);
        cp16(dst + 3*TILE_B,     bLg + go);  cp16(dst + 3*TILE_B + 16,  bLg + go + 8);
        cp_commit();
    }

    for (int c = 0; c < NCH; c++) {
        cp_wait<2>();
        __syncthreads();

        const uint32_t cur = sb + (c & 3) * STG_B;
        #pragma unroll
        for (int ks = 0; ks < 2; ks++) {
            uint32_t ah[4][4], al[4][4], bh[4][2], bl[4][2];
            #pragma unroll
            for (int mi = 0; mi < 4; mi++) {
                const uint32_t off = (uint32_t)(((wm*64 + mi*16 + la_r)*SA + ks*16 + la_k) * 2);
                ldsm4(cur + off,          ah[mi]);
                ldsm4(cur + TILE_B + off, al[mi]);
            }
            #pragma unroll
            for (int p = 0; p < 2; p++) {
                const uint32_t off = (uint32_t)(((wn*32 + p*16 + lb_c)*SA + ks*16 + lb_k) * 2);
                uint32_t t[4];
                ldsm4(cur + 2*TILE_B + off, t);
                bh[2*p][0] = t[0]; bh[2*p][1] = t[1];
                bh[2*p+1][0] = t[2]; bh[2*p+1][1] = t[3];
                ldsm4(cur + 3*TILE_B + off, t);
                bl[2*p][0] = t[0]; bl[2*p][1] = t[1];
                bl[2*p+1][0] = t[2]; bl[2*p+1][1] = t[3];
            }
            #pragma unroll
            for (int mi = 0; mi < 4; mi++)
                #pragma unroll
                for (int ni = 0; ni < 4; ni++) {
                    mma16816(acc[mi][ni], ah[mi], bh[ni]);
                    mma16816(acc[mi][ni], al[mi], bh[ni]);
                    mma16816(acc[mi][ni], ah[mi], bl[ni]);
                }
        }

        if (c + 3 < NCH) {
            const uint32_t dst = sb + ((c+3) & 3) * STG_B + dsto;
            const size_t go = (size_t)(c+3) * 32;
            cp16(dst,                aHg + go);  cp16(dst + 16,             aHg + go + 8);
            cp16(dst +   TILE_B,     aLg + go);  cp16(dst +   TILE_B + 16,  aLg + go + 8);
            cp16(dst + 2*TILE_B,     bHg + go);  cp16(dst + 2*TILE_B + 16,  bHg + go + 8);
            cp16(dst + 3*TILE_B,     bLg + go);  cp16(dst + 3*TILE_B + 16,  bLg + go + 8);
        }
        cp_commit();
    }

    // epilogue
    const bool ROPE = (MODE == 1) || (MODE == 2);
    #pragma unroll
    for (int mi = 0; mi < 4; mi++) {
        const int gr0 = row0 + wm*64 + mi*16 + (lane >> 2);
        const int gr1 = gr0 + 8;
        #pragma unroll
        for (int ni = 0; ni < 4; ni++) {
            const int gc = col0 + wn*32 + ni*8 + (lane & 3)*2;
            float c0 = acc[mi][ni][0], c1 = acc[mi][ni][1];
            float c2 = acc[mi][ni][2], c3 = acc[mi][ni][3];
            if (ROPE) {
                const int ip = (gc & (DKv - 1)) >> 1;
                const int s0 = gr0 & (Sv - 1), s1 = gr1 & (Sv - 1);
                float ca = fc[s0*64 + ip], sa = fs[s0*64 + ip];
                float cb = fc[s1*64 + ip], sb2 = fs[s1*64 + ip];
                float t0 = c0*ca - c1*sa, t1 = c0*sa + c1*ca;
                float t2 = c2*cb - c3*sb2, t3 = c2*sb2 + c3*cb;
                c0 = t0; c1 = t1; c2 = t2; c3 = t3;
            }
            if (MODE == 1) {
                const float s = 0.08838834764831845f;   // 1/sqrt(128)
                c0 *= s; c1 *= s; c2 *= s; c3 *= s;
            }
            if (MODE != 1) {
                float2 r0; r0.x = c0; r0.y = c1;
                float2 r1; r1.x = c2; r1.y = c3;
                *(float2*)(C + (size_t)gr0 * Dv + gc) = r0;
                *(float2*)(C + (size_t)gr1 * Dv + gc) = r1;
            }
            if (MODE >= 1) {
                uint32_t h0, l0, h1, l1;
                split2(c0, c1, h0, l0);
                split2(c2, c3, h1, l1);
                *(uint32_t*)(Ph + (size_t)gr0 * Dv + gc) = h0;
                *(uint32_t*)(Pl + (size_t)gr0 * Dv + gc) = l0;
                *(uint32_t*)(Ph + (size_t)gr1 * Dv + gc) = h1;
                *(uint32_t*)(Pl + (size_t)gr1 * Dv + gc) = l1;
            }
        }
    }
}

// ---------------------------------------------------------------------------
// Tensor-core flash attention on pre-split bf16 hi/lo planes.
// No converts in the loop: cp.async loads, K overlaps PV, V overlaps QK.
// 64 q-rows/CTA, 128 threads (4 warps x 16 rows), 2 CTAs/SM.
// ---------------------------------------------------------------------------
#define SP      136
#define ATILE   (64*SP*2)        // 17408 B
#define ASM_TOT (6*ATILE)        // 104448 B

__global__ __launch_bounds__(128, 2)
void attn_mma(const __nv_bfloat16* __restrict__ Qh, const __nv_bfloat16* __restrict__ Ql,
              const __nv_bfloat16* __restrict__ Kh, const __nv_bfloat16* __restrict__ Kl,
              const __nv_bfloat16* __restrict__ Vh, const __nv_bfloat16* __restrict__ Vl,
              __nv_bfloat16* __restrict__ ch, __nv_bfloat16* __restrict__ cl)
{
    extern __shared__ __align__(16) char smem[];
    const uint32_t sb = smem_u32(smem);
    const int tid  = threadIdx.x;
    const int lane = tid & 31;
    const int warp = tid >> 5;
    const int qt   = blockIdx.x;
    const int q0   = qt * 64;
    const int h    = blockIdx.y;
    const int b    = blockIdx.z;
    const size_t hoff = (size_t)h * DKv;

    const uint32_t QH = 0, QL = ATILE, KH = 2*ATILE, KL = 3*ATILE,
                   VH = 4*ATILE, VL = 5*ATILE;

    // loader addressing: thread -> (row, 64-wide half)
    const int lr  = tid >> 1;
    const int lc0 = (tid & 1) * 64;
    const uint32_t drow = (uint32_t)(lr*SP + lc0) * 2;
    const size_t qoff = (size_t)(b*Sv + q0 + lr) * Dv + hoff + lc0;
    const size_t koff0 = (size_t)(b*Sv + lr) * Dv + hoff + lc0;   // + kt*64*Dv

    // prologue: Q + K_0 in one group
    #pragma unroll
    for (int u = 0; u < 8; u++) {
        cp16(sb + QH + drow + u*16, Qh + qoff + u*8);
        cp16(sb + QL + drow + u*16, Ql + qoff + u*8);
        cp16(sb + KH + drow + u*16, Kh + koff0 + u*8);
        cp16(sb + KL + drow + u*16, Kl + koff0 + u*8);
    }
    cp_commit();

    float ctxa[16][4];
    #pragma unroll
    for (int i = 0; i < 16; i++)
        #pragma unroll
        for (int j = 0; j < 4; j++) ctxa[i][j] = 0.0f;
    float m0 = -1e30f, m1 = -1e30f, l0 = 0.0f, l1 = 0.0f;

    for (int kt = 0; kt <= qt; kt++) {
        // V_kt (overlaps QK below); barrier first: prev PV must be done with V smem
        __syncthreads();
        {
            const size_t vo = koff0 + (size_t)kt*64*Dv;
            #pragma unroll
            for (int u = 0; u < 8; u++) {
                cp16(sb + VH + drow + u*16, Vh + vo + u*8);
                cp16(sb + VL + drow + u*16, Vl + vo + u*8);
            }
        }
        cp_commit();
        cp_wait<1>();        // K_kt (and Q) ready; V may still be in flight
        __syncthreads();

        // ---- scores: S[16 x 64] per warp over dk=128, hi/lo 3-term ----
        float sc[8][4];
        #pragma unroll
        for (int nt = 0; nt < 8; nt++)
            #pragma unroll
            for (int j = 0; j < 4; j++) sc[nt][j] = 0.0f;

        #pragma unroll
        for (int ks = 0; ks < 8; ks++) {
            uint32_t qh[4], ql[4];
            const uint32_t qaddr = sb + QH +
                (uint32_t)(((warp*16 + (lane & 15))*SP + ks*16 + (lane >> 4)*8) * 2);
            ldsm4(qaddr,         qh);
            ldsm4(qaddr + ATILE, ql);
            #pragma unroll
            for (int p = 0; p < 4; p++) {
                const uint32_t kaddr = sb + KH +
                    (uint32_t)(((p*16 + (lane & 15))*SP + ks*16 + (lane >> 4)*8) * 2);
                uint32_t th[4], tl[4];
                ldsm4(kaddr,         th);
                ldsm4(kaddr + ATILE, tl);
                uint32_t bh0[2] = {th[0], th[2]}, bh1[2] = {th[1], th[3]};
                uint32_t bl0[2] = {tl[0], tl[2]}, bl1[2] = {tl[1], tl[3]};
                mma16816(sc[2*p],   qh, bh0);
                mma16816(sc[2*p],   ql, bh0);
                mma16816(sc[2*p],   qh, bl0);
                mma16816(sc[2*p+1], qh, bh1);
                mma16816(sc[2*p+1], ql, bh1);
                mma16816(sc[2*p+1], qh, bl1);
            }
        }

        // ---- softmax ----
        const int gr0 = q0 + warp*16 + (lane >> 2);
        const int gr1 = gr0 + 8;
        if (kt == qt) {
            #pragma unroll
            for (int nt = 0; nt < 8; nt++) {
                const int cb = kt*64 + nt*8 + (lane & 3)*2;
                if (cb     > gr0) sc[nt][0] = -1e30f;
                if (cb + 1 > gr0) sc[nt][1] = -1e30f;
                if (cb     > gr1) sc[nt][2] = -1e30f;
                if (cb + 1 > gr1) sc[nt][3] = -1e30f;
            }
        }
        float mx0 = -1e30f, mx1 = -1e30f;
        #pragma unroll
        for (int nt = 0; nt < 8; nt++) {
            mx0 = fmaxf(mx0, fmaxf(sc[nt][0], sc[nt][1]));
            mx1 = fmaxf(mx1, fmaxf(sc[nt][2], sc[nt][3]));
        }
        mx0 = fmaxf(mx0, __shfl_xor_sync(0xffffffffu, mx0, 1));
        mx0 = fmaxf(mx0, __shfl_xor_sync(0xffffffffu, mx0, 2));
        mx1 = fmaxf(mx1, __shfl_xor_sync(0xffffffffu, mx1, 1));
        mx1 = fmaxf(mx1, __shfl_xor_sync(0xffffffffu, mx1, 2));

        const float mn0 = fmaxf(m0, mx0), mn1 = fmaxf(m1, mx1);
        const float a0 = __expf(m0 - mn0), a1 = __expf(m1 - mn1);
        m0 = mn0; m1 = mn1;

        float s0 = 0.0f, s1 = 0.0f;
        #pragma unroll
        for (int nt = 0; nt < 8; nt++) {
            sc[nt][0] = __expf(sc[nt][0] - mn0);
            sc[nt][1] = __expf(sc[nt][1] - mn0);
            sc[nt][2] = __expf(sc[nt][2] - mn1);
            sc[nt][3] = __expf(sc[nt][3] - mn1);
            s0 += sc[nt][0] + sc[nt][1];
            s1 += sc[nt][2] + sc[nt][3];
        }
        s0 += __shfl_xor_sync(0xffffffffu, s0, 1);
        s0 += __shfl_xor_sync(0xffffffffu, s0, 2);
        s1 += __shfl_xor_sync(0xffffffffu, s1, 1);
        s1 += __shfl_xor_sync(0xffffffffu, s1, 2);
        l0 = l0 * a0 + s0;
        l1 = l1 * a1 + s1;

        #pragma unroll
        for (int nt = 0; nt < 16; nt++) {
            ctxa[nt][0] *= a0; ctxa[nt][1] *= a0;
            ctxa[nt][2] *= a1; ctxa[nt][3] *= a1;
        }

        // pack P (C-frag -> A-frag), hi/lo
        uint32_t pah[4][4], pal[4][4];
        #pragma unroll
        for (int k2 = 0; k2 < 4; k2++) {
            split2(sc[2*k2][0],   sc[2*k2][1],   pah[k2][0], pal[k2][0]);
            split2(sc[2*k2][2],   sc[2*k2][3],   pah[k2][1], pal[k2][1]);
            split2(sc[2*k2+1][0], sc[2*k2+1][1], pah[k2][2], pal[k2][2]);
            split2(sc[2*k2+1][2], sc[2*k2+1][3], pah[k2][3], pal[k2][3]);
        }

        // all warps done reading K smem -> safe to start K_{kt+1}
        __syncthreads();
        if (kt < qt) {
            const size_t ko = koff0 + (size_t)(kt+1)*64*Dv;
            #pragma unroll
            for (int u = 0; u < 8; u++) {
                cp16(sb + KH + drow + u*16, Kh + ko + u*8);
                cp16(sb + KL + drow + u*16, Kl + ko + u*8);
            }
        }
        cp_commit();          // unconditional: keeps group numbering exact
        cp_wait<1>();         // V_kt ready; K_{kt+1} may still be in flight
        __syncthreads();

        // ---- ctx += P @ V  (V via ldmatrix.trans) ----
        #pragma unroll
        for (int k2 = 0; k2 < 4; k2++) {
            #pragma unroll
            for (int p = 0; p < 8; p++) {
                const uint32_t vaddr = sb + VH +
                    (uint32_t)(((k2*16 + (lane & 15))*SP + p*16 + (lane >> 4)*8) * 2);
                uint32_t vh[4], vl[4];
                ldsm4t(vaddr,         vh);
                ldsm4t(vaddr + ATILE, vl);
                uint32_t bh0[2] = {vh[0], vh[1]}, bh1[2] = {vh[2], vh[3]};
                uint32_t bl0[2] = {vl[0], vl[1]}, bl1[2] = {vl[2], vl[3]};
                mma16816(ctxa[2*p],   pah[k2], bh0);
                mma16816(ctxa[2*p],   pal[k2], bh0);
                mma16816(ctxa[2*p],   pah[k2], bl0);
                mma16816(ctxa[2*p+1], pah[k2], bh1);
                mma16816(ctxa[2*p+1], pal[k2], bh1);
                mma16816(ctxa[2*p+1], pah[k2], bl1);
            }
        }
    }

    // epilogue: ctx/l -> bf16 hi/lo planes
    const float i0 = 1.0f / l0, i1 = 1.0f / l1;
    const size_t r0g = (size_t)(b*Sv + q0 + warp*16 + (lane >> 2));
    const size_t r1g = r0g + 8;
    #pragma unroll
    for (int nt = 0; nt < 16; nt++) {
        const size_t col = hoff + nt*8 + (lane & 3)*2;
        uint32_t h0, l0u, h1, l1u;
        split2(ctxa[nt][0]*i0, ctxa[nt][1]*i0, h0, l0u);
        split2(ctxa[nt][2]*i1, ctxa[nt][3]*i1, h1, l1u);
        *(uint32_t*)(ch + r0g*Dv + col) = h0;
        *(uint32_t*)(cl + r0g*Dv + col) = l0u;
        *(uint32_t*)(ch + r1g*Dv + col) = h1;
        *(uint32_t*)(cl + r1g*Dv + col) = l1u;
    }
}

// ---------------------------------------------------------------------------
extern "C" void kernel_launch(void* const* d_in, const int* in_sizes, int n_in,
                              void* d_out, int out_size)
{
    const float* x  = (const float*)d_in[0];
    const float* fc = (const float*)d_in[1];
    const float* fs = (const float*)d_in[2];
    // d_in[3] = mask (unused: -1e9 mask == strict causal in f32)
    const float* Wq = (const float*)d_in[4];
    const float* Wk = (const float*)d_in[5];
    const float* Wv = (const float*)d_in[6];
    const float* Wo = (const float*)d_in[7];

    float* out  = (float*)d_out;
    float* outK = out  + (size_t)Mv*Dv;
    float* outV = outK + (size_t)Mv*Dv;

    __nv_bfloat16 *xh, *xl, *wh, *wl, *qh, *ql, *kh, *kl, *vh, *vl, *ch, *cl;
    cudaGetSymbolAddress((void**)&xh, g_xh);
    cudaGetSymbolAddress((void**)&xl, g_xl);
    cudaGetSymbolAddress((void**)&wh, g_wh);
    cudaGetSymbolAddress((void**)&wl, g_wl);
    cudaGetSymbolAddress((void**)&qh, g_qh);
    cudaGetSymbolAddress((void**)&ql, g_ql);
    cudaGetSymbolAddress((void**)&kh, g_kh);
    cudaGetSymbolAddress((void**)&kl, g_kl);
    cudaGetSymbolAddress((void**)&vh, g_vh);
    cudaGetSymbolAddress((void**)&vl, g_vl);
    cudaGetSymbolAddress((void**)&ch, g_ch);
    cudaGetSymbolAddress((void**)&cl, g_cl);

    cudaFuncSetAttribute(gemm_bf<0>, cudaFuncAttributeMaxDynamicSharedMemorySize, GSM_TOTAL);
    cudaFuncSetAttribute(gemm_bf<1>, cudaFuncAttributeMaxDynamicSharedMemorySize, GSM_TOTAL);
    cudaFuncSetAttribute(gemm_bf<2>, cudaFuncAttributeMaxDynamicSharedMemorySize, GSM_TOTAL);
    cudaFuncSetAttribute(gemm_bf<3>, cudaFuncAttributeMaxDynamicSharedMemorySize, GSM_TOTAL);
    cudaFuncSetAttribute(attn_mma,   cudaFuncAttributeMaxDynamicSharedMemorySize, ASM_TOT);

    const size_t WN = (size_t)Dv*Dv;     // 4M elems per weight

    split_k<<<(Mv*Dv/8 + 255)/256, 256>>>(x,  xh, xl, Mv*Dv/8);
    split_k<<<(WN/8 + 255)/256, 256>>>(Wq, wh,        wl,        (int)(WN/8));
    split_k<<<(WN/8 + 255)/256, 256>>>(Wk, wh + WN,   wl + WN,   (int)(WN/8));
    split_k<<<(WN/8 + 255)/256, 256>>>(Wv, wh + 2*WN, wl + 2*WN, (int)(WN/8));
    split_k<<<(WN/8 + 255)/256, 256>>>(Wo, wh + 3*WN, wl + 3*WN, (int)(WN/8));

    dim3 ggrid(Dv/128, Mv/128);   // (16, 32)
    gemm_bf<1><<<ggrid, 256, GSM_TOTAL>>>(xh, xl, wh,        wl,        fc, fs, nullptr, qh, ql);
    gemm_bf<2><<<ggrid, 256, GSM_TOTAL>>>(xh, xl, wh + WN,   wl + WN,   fc, fs, outK,    kh, kl);
    gemm_bf<3><<<ggrid, 256, GSM_TOTAL>>>(xh, xl, wh + 2*WN, wl + 2*WN, fc, fs, outV,    vh, vl);

    attn_mma<<<dim3(Sv/64, Hv, Bv), 128, ASM_TOT>>>(qh, ql, kh, kl, vh, vl, ch, cl);

    gemm_bf<0><<<ggrid, 256, GSM_TOTAL>>>(ch, cl, wh + 3*WN, wl + 3*WN, fc, fs, out, nullptr, nullptr);
}

// round 11
// speedup vs baseline: 3.2039x; 1.0937x over previous
#include <cuda_runtime.h>
#include <cuda_bf16.h>
#include <math.h>
#include <stdint.h>

#define Bv  2
#define Sv  2048
#define Dv  2048
#define Hv  16
#define DKv 128
#define Mv  (Bv*Sv)   // 4096

// Scratch (allocation-free rule: __device__ globals)
__device__ __nv_bfloat16 g_xh[(size_t)Mv*Dv];              // x hi
__device__ __nv_bfloat16 g_xl[(size_t)Mv*Dv];              // x lo
__device__ __nv_bfloat16 g_wh[(size_t)4*Dv*Dv];            // Wq|Wk|Wv|Wo hi
__device__ __nv_bfloat16 g_wl[(size_t)4*Dv*Dv];            // Wq|Wk|Wv|Wo lo
__device__ __nv_bfloat16 g_qh[(size_t)Mv*Dv];              // Q (rope, scaled) hi
__device__ __nv_bfloat16 g_ql[(size_t)Mv*Dv];              // Q lo
__device__ __nv_bfloat16 g_kh[(size_t)Mv*Dv];              // K (rope) hi
__device__ __nv_bfloat16 g_kl[(size_t)Mv*Dv];              // K lo
__device__ __nv_bfloat16 g_vh[(size_t)Mv*Dv];              // V hi
__device__ __nv_bfloat16 g_vl[(size_t)Mv*Dv];              // V lo
__device__ __nv_bfloat16 g_ch[(size_t)Mv*Dv];              // ctx hi
__device__ __nv_bfloat16 g_cl[(size_t)Mv*Dv];              // ctx lo

// ---------------------------------------------------------------------------
// helpers
// ---------------------------------------------------------------------------
__device__ __forceinline__ uint32_t smem_u32(const void* p){
    uint32_t a;
    asm("{ .reg .u64 t; cvta.to.shared.u64 t, %1; cvt.u32.u64 %0, t; }" : "=r"(a) : "l"(p));
    return a;
}
__device__ __forceinline__ uint32_t pack_bf2(float x, float y){
    __nv_bfloat162 h = __floats2bfloat162_rn(x, y);
    return *reinterpret_cast<uint32_t*>(&h);
}
__device__ __forceinline__ void ldsm4(uint32_t addr, uint32_t r[4]){
    asm volatile("ldmatrix.sync.aligned.m8n8.x4.shared.b16 {%0,%1,%2,%3}, [%4];"
                 : "=r"(r[0]), "=r"(r[1]), "=r"(r[2]), "=r"(r[3]) : "r"(addr));
}
__device__ __forceinline__ void ldsm4t(uint32_t addr, uint32_t r[4]){
    asm volatile("ldmatrix.sync.aligned.m8n8.x4.trans.shared.b16 {%0,%1,%2,%3}, [%4];"
                 : "=r"(r[0]), "=r"(r[1]), "=r"(r[2]), "=r"(r[3]) : "r"(addr));
}
__device__ __forceinline__ void mma16816(float c[4], const uint32_t a[4], const uint32_t b[2]){
    asm volatile(
        "mma.sync.aligned.m16n8k16.row.col.f32.bf16.bf16.f32 "
        "{%0,%1,%2,%3}, {%4,%5,%6,%7}, {%8,%9}, {%0,%1,%2,%3};"
        : "+f"(c[0]), "+f"(c[1]), "+f"(c[2]), "+f"(c[3])
        : "r"(a[0]), "r"(a[1]), "r"(a[2]), "r"(a[3]), "r"(b[0]), "r"(b[1]));
}
__device__ __forceinline__ void split2(float x, float y, uint32_t& hi, uint32_t& lo){
    float hx = __bfloat162float(__float2bfloat16(x));
    float hy = __bfloat162float(__float2bfloat16(y));
    hi = pack_bf2(hx, hy);
    lo = pack_bf2(x - hx, y - hy);
}
__device__ __forceinline__ void cp16(uint32_t dst, const void* src){
    asm volatile("cp.async.cg.shared.global [%0], [%1], 16;" :: "r"(dst), "l"(src));
}
__device__ __forceinline__ void cp_commit(){
    asm volatile("cp.async.commit_group;" ::: "memory");
}
template<int N>
__device__ __forceinline__ void cp_wait(){
    asm volatile("cp.async.wait_group %0;" :: "n"(N) : "memory");
}

// ---------------------------------------------------------------------------
// fp32 -> bf16 hi/lo planes
// ---------------------------------------------------------------------------
__global__ __launch_bounds__(256)
void split_x(const float* __restrict__ src, __nv_bfloat16* __restrict__ hi,
             __nv_bfloat16* __restrict__ lo, int n8)
{
    const int i = blockIdx.x * blockDim.x + threadIdx.x;
    if (i >= n8) return;
    const float4* s = (const float4*)src + 2*(size_t)i;
    float4 v0 = s[0], v1 = s[1];
    uint32_t h[4], l[4];
    split2(v0.x, v0.y, h[0], l[0]); split2(v0.z, v0.w, h[1], l[1]);
    split2(v1.x, v1.y, h[2], l[2]); split2(v1.z, v1.w, h[3], l[3]);
    ((uint4*)hi)[i] = make_uint4(h[0], h[1], h[2], h[3]);
    ((uint4*)lo)[i] = make_uint4(l[0], l[1], l[2], l[3]);
}

// all 4 weights in one launch (dst planes are contiguous)
__global__ __launch_bounds__(256)
void split_w4(const float* __restrict__ s0, const float* __restrict__ s1,
              const float* __restrict__ s2, const float* __restrict__ s3,
              __nv_bfloat16* __restrict__ hi, __nv_bfloat16* __restrict__ lo)
{
    const size_t i = (size_t)blockIdx.x * blockDim.x + threadIdx.x;  // < 4*WN/8
    const int sel = (int)(i >> 19);                  // WN/8 = 524288 per weight
    const size_t local = i & 524287u;
    const float* src = (sel == 0) ? s0 : (sel == 1) ? s1 : (sel == 2) ? s2 : s3;
    const float4* s = (const float4*)src + 2*local;
    float4 v0 = s[0], v1 = s[1];
    uint32_t h[4], l[4];
    split2(v0.x, v0.y, h[0], l[0]); split2(v0.z, v0.w, h[1], l[1]);
    split2(v1.x, v1.y, h[2], l[2]); split2(v1.z, v1.w, h[3], l[3]);
    ((uint4*)hi)[i] = make_uint4(h[0], h[1], h[2], h[3]);
    ((uint4*)lo)[i] = make_uint4(l[0], l[1], l[2], l[3]);
}

// ---------------------------------------------------------------------------
// Pipelined bf16 GEMM mainloop (3-term hi/lo), shared by QKV + Wo kernels.
// 128x128 tile, BK=32, 256 threads (8 warps 2x4), 4-stage cp.async pipeline.
// ---------------------------------------------------------------------------
#define SA      40
#define TILE_B  (128*SA*2)      // 10240 B
#define STG_B   (4*TILE_B)      // 40960 B
#define GSM_TOTAL (4*STG_B)     // 163840 B
#define NCH     (Dv/32)         // 64

struct GemmCore {
    float acc[4][4][4];
    int wm, wn, lane;

    __device__ __forceinline__ void run(char* smem,
        const __nv_bfloat16* Ah, const __nv_bfloat16* Al,
        const __nv_bfloat16* Bh, const __nv_bfloat16* Bl,
        int row0, int col0, int tid)
    {
        lane = tid & 31;
        const int wid = tid >> 5;
        wm = wid >> 2;
        wn = wid & 3;
        #pragma unroll
        for (int i = 0; i < 4; i++)
            #pragma unroll
            for (int j = 0; j < 4; j++)
                #pragma unroll
                for (int q = 0; q < 4; q++) acc[i][j][q] = 0.0f;

        const int la_r = (lane & 7) + ((lane >> 3) & 1) * 8;
        const int la_k = (lane >> 4) * 8;
        const int lb_c = (lane & 7) + (lane >> 4) * 8;
        const int lb_k = ((lane >> 3) & 1) * 8;

        const int lrow  = tid >> 1;
        const int lhalf = tid & 1;
        const __nv_bfloat16* aHg = Ah + (size_t)(row0 + lrow) * Dv + lhalf*16;
        const __nv_bfloat16* aLg = Al + (size_t)(row0 + lrow) * Dv + lhalf*16;
        const __nv_bfloat16* bHg = Bh + (size_t)(col0 + lrow) * Dv + lhalf*16;
        const __nv_bfloat16* bLg = Bl + (size_t)(col0 + lrow) * Dv + lhalf*16;
        const uint32_t dsto = (uint32_t)(lrow*(SA*2) + lhalf*32);
        const uint32_t sb = smem_u32(smem);

        #pragma unroll
        for (int s = 0; s < 3; s++) {
            const uint32_t dst = sb + s*STG_B + dsto;
            const size_t go = (size_t)s * 32;
            cp16(dst,               aHg + go);  cp16(dst + 16,            aHg + go + 8);
            cp16(dst +   TILE_B,    aLg + go);  cp16(dst +   TILE_B + 16, aLg + go + 8);
            cp16(dst + 2*TILE_B,    bHg + go);  cp16(dst + 2*TILE_B + 16, bHg + go + 8);
            cp16(dst + 3*TILE_B,    bLg + go);  cp16(dst + 3*TILE_B + 16, bLg + go + 8);
            cp_commit();
        }

        for (int c = 0; c < NCH; c++) {
            cp_wait<2>();
            __syncthreads();

            const uint32_t cur = sb + (c & 3) * STG_B;
            #pragma unroll
            for (int ks = 0; ks < 2; ks++) {
                uint32_t ah[4][4], al[4][4], bh[4][2], bl[4][2];
                #pragma unroll
                for (int mi = 0; mi < 4; mi++) {
                    const uint32_t off = (uint32_t)(((wm*64 + mi*16 + la_r)*SA + ks*16 + la_k) * 2);
                    ldsm4(cur + off,          ah[mi]);
                    ldsm4(cur + TILE_B + off, al[mi]);
                }
                #pragma unroll
                for (int p = 0; p < 2; p++) {
                    const uint32_t off = (uint32_t)(((wn*32 + p*16 + lb_c)*SA + ks*16 + lb_k) * 2);
                    uint32_t t[4];
                    ldsm4(cur + 2*TILE_B + off, t);
                    bh[2*p][0] = t[0]; bh[2*p][1] = t[1];
                    bh[2*p+1][0] = t[2]; bh[2*p+1][1] = t[3];
                    ldsm4(cur + 3*TILE_B + off, t);
                    bl[2*p][0] = t[0]; bl[2*p][1] = t[1];
                    bl[2*p+1][0] = t[2]; bl[2*p+1][1] = t[3];
                }
                #pragma unroll
                for (int mi = 0; mi < 4; mi++)
                    #pragma unroll
                    for (int ni = 0; ni < 4; ni++) {
                        mma16816(acc[mi][ni], ah[mi], bh[ni]);
                        mma16816(acc[mi][ni], al[mi], bh[ni]);
                        mma16816(acc[mi][ni], ah[mi], bl[ni]);
                    }
            }

            if (c + 3 < NCH) {
                const uint32_t dst = sb + ((c+3) & 3) * STG_B + dsto;
                const size_t go = (size_t)(c+3) * 32;
                cp16(dst,               aHg + go);  cp16(dst + 16,            aHg + go + 8);
                cp16(dst +   TILE_B,    aLg + go);  cp16(dst +   TILE_B + 16, aLg + go + 8);
                cp16(dst + 2*TILE_B,    bHg + go);  cp16(dst + 2*TILE_B + 16, bHg + go + 8);
                cp16(dst + 3*TILE_B,    bLg + go);  cp16(dst + 3*TILE_B + 16, bLg + go + 8);
            }
            cp_commit();
        }
    }
};

// Merged Q/K/V projection GEMM: blockIdx.z = 0(Q) / 1(K) / 2(V)
__global__ __launch_bounds__(256, 1)
void gemm_qkv(const __nv_bfloat16* __restrict__ xh, const __nv_bfloat16* __restrict__ xl,
              const __nv_bfloat16* __restrict__ wh, const __nv_bfloat16* __restrict__ wl,
              const float* __restrict__ fc, const float* __restrict__ fs,
              float* __restrict__ outK, float* __restrict__ outV,
              __nv_bfloat16* __restrict__ qh, __nv_bfloat16* __restrict__ ql,
              __nv_bfloat16* __restrict__ kh, __nv_bfloat16* __restrict__ kl,
              __nv_bfloat16* __restrict__ vh, __nv_bfloat16* __restrict__ vl)
{
    extern __shared__ __align__(1024) char smem[];
    const int z    = blockIdx.z;
    const int row0 = blockIdx.y * 128;
    const int col0 = blockIdx.x * 128;
    const size_t WN = (size_t)Dv*Dv;

    GemmCore core;
    core.run(smem, xh, xl, wh + (size_t)z*WN, wl + (size_t)z*WN, row0, col0, threadIdx.x);

    float* Cf = (z == 1) ? outK : (z == 2) ? outV : nullptr;
    __nv_bfloat16* Ph = (z == 0) ? qh : (z == 1) ? kh : vh;
    __nv_bfloat16* Pl = (z == 0) ? ql : (z == 1) ? kl : vl;
    const bool ROPE = (z <= 1);
    const int lane = core.lane;

    #pragma unroll
    for (int mi = 0; mi < 4; mi++) {
        const int gr0 = row0 + core.wm*64 + mi*16 + (lane >> 2);
        const int gr1 = gr0 + 8;
        #pragma unroll
        for (int ni = 0; ni < 4; ni++) {
            const int gc = col0 + core.wn*32 + ni*8 + (lane & 3)*2;
            float c0 = core.acc[mi][ni][0], c1 = core.acc[mi][ni][1];
            float c2 = core.acc[mi][ni][2], c3 = core.acc[mi][ni][3];
            if (ROPE) {
                const int ip = (gc & (DKv - 1)) >> 1;
                const int s0 = gr0 & (Sv - 1), s1 = gr1 & (Sv - 1);
                float ca = fc[s0*64 + ip], sa = fs[s0*64 + ip];
                float cb = fc[s1*64 + ip], sb2 = fs[s1*64 + ip];
                float t0 = c0*ca - c1*sa, t1 = c0*sa + c1*ca;
                float t2 = c2*cb - c3*sb2, t3 = c2*sb2 + c3*cb;
                c0 = t0; c1 = t1; c2 = t2; c3 = t3;
            }
            if (z == 0) {
                const float s = 0.08838834764831845f;   // 1/sqrt(128)
                c0 *= s; c1 *= s; c2 *= s; c3 *= s;
            } else {
                float2 r0; r0.x = c0; r0.y = c1;
                float2 r1; r1.x = c2; r1.y = c3;
                *(float2*)(Cf + (size_t)gr0 * Dv + gc) = r0;
                *(float2*)(Cf + (size_t)gr1 * Dv + gc) = r1;
            }
            uint32_t h0, l0, h1, l1;
            split2(c0, c1, h0, l0);
            split2(c2, c3, h1, l1);
            *(uint32_t*)(Ph + (size_t)gr0 * Dv + gc) = h0;
            *(uint32_t*)(Pl + (size_t)gr0 * Dv + gc) = l0;
            *(uint32_t*)(Ph + (size_t)gr1 * Dv + gc) = h1;
            *(uint32_t*)(Pl + (size_t)gr1 * Dv + gc) = l1;
        }
    }
}

// Wo GEMM: fp32 out only
__global__ __launch_bounds__(256, 1)
void gemm_wo(const __nv_bfloat16* __restrict__ Ah, const __nv_bfloat16* __restrict__ Al,
             const __nv_bfloat16* __restrict__ Bh, const __nv_bfloat16* __restrict__ Bl,
             float* __restrict__ C)
{
    extern __shared__ __align__(1024) char smem[];
    const int row0 = blockIdx.y * 128;
    const int col0 = blockIdx.x * 128;

    GemmCore core;
    core.run(smem, Ah, Al, Bh, Bl, row0, col0, threadIdx.x);

    const int lane = core.lane;
    #pragma unroll
    for (int mi = 0; mi < 4; mi++) {
        const int gr0 = row0 + core.wm*64 + mi*16 + (lane >> 2);
        const int gr1 = gr0 + 8;
        #pragma unroll
        for (int ni = 0; ni < 4; ni++) {
            const int gc = col0 + core.wn*32 + ni*8 + (lane & 3)*2;
            float2 r0; r0.x = core.acc[mi][ni][0]; r0.y = core.acc[mi][ni][1];
            float2 r1; r1.x = core.acc[mi][ni][2]; r1.y = core.acc[mi][ni][3];
            *(float2*)(C + (size_t)gr0 * Dv + gc) = r0;
            *(float2*)(C + (size_t)gr1 * Dv + gc) = r1;
        }
    }
}

// ---------------------------------------------------------------------------
// Tensor-core flash attention, BM=128 q-rows/CTA, 256 threads (8 warps x 16
// rows), kv tiles 64 wide. Pure cp.async + LDSM + HMMA mainloop.
// SMEM: Q hi/lo [128][136] + K,V hi/lo [64][136] = 139264 B -> 1 CTA/SM.
// ---------------------------------------------------------------------------
#define SP      136
#define QTILE   (128*SP*2)       // 34816 B
#define KTILE   (64*SP*2)        // 17408 B
#define ASM_TOT (2*QTILE + 4*KTILE)   // 139264 B

__global__ __launch_bounds__(256, 1)
void attn_mma(const __nv_bfloat16* __restrict__ Qh, const __nv_bfloat16* __restrict__ Ql,
              const __nv_bfloat16* __restrict__ Kh, const __nv_bfloat16* __restrict__ Kl,
              const __nv_bfloat16* __restrict__ Vh, const __nv_bfloat16* __restrict__ Vl,
              __nv_bfloat16* __restrict__ ch, __nv_bfloat16* __restrict__ cl)
{
    extern __shared__ __align__(16) char smem[];
    const uint32_t sb = smem_u32(smem);
    const int tid  = threadIdx.x;
    const int lane = tid & 31;
    const int warp = tid >> 5;           // 0..7
    const int qt   = blockIdx.x;
    const int q0   = qt * 128;
    const int h    = blockIdx.y;
    const int b    = blockIdx.z;
    const size_t hoff = (size_t)h * DKv;

    const uint32_t QH = 0, QL = QTILE, KH = 2*QTILE, VH = 2*QTILE + 2*KTILE;
    // (K lo at KH+KTILE, V lo at VH+KTILE)

    // Q loader: 256 threads -> 128 rows x 2 halves
    const int lrq = tid >> 1;
    const int lcq = (tid & 1) * 64;
    const uint32_t drq = (uint32_t)(lrq*SP + lcq) * 2;
    const size_t qoff = (size_t)(b*Sv + q0 + lrq) * Dv + hoff + lcq;
    // K/V loader: 256 threads -> 64 rows x 4 quarters
    const int lrk = tid >> 2;
    const int lck = (tid & 3) * 32;
    const uint32_t drk = (uint32_t)(lrk*SP + lck) * 2;
    const size_t koff0 = (size_t)(b*Sv + lrk) * Dv + hoff + lck;   // + kt*64*Dv

    // prologue: Q + K_0 in one group
    #pragma unroll
    for (int u = 0; u < 8; u++) {
        cp16(sb + QH + drq + u*16, Qh + qoff + u*8);
        cp16(sb + QL + drq + u*16, Ql + qoff + u*8);
    }
    #pragma unroll
    for (int u = 0; u < 4; u++) {
        cp16(sb + KH +         drk + u*16, Kh + koff0 + u*8);
        cp16(sb + KH + KTILE + drk + u*16, Kl + koff0 + u*8);
    }
    cp_commit();

    float ctxa[16][4];
    #pragma unroll
    for (int i = 0; i < 16; i++)
        #pragma unroll
        for (int j = 0; j < 4; j++) ctxa[i][j] = 0.0f;
    float m0 = -1e30f, m1 = -1e30f, l0 = 0.0f, l1 = 0.0f;

    const int ktmax = 2*qt + 1;
    for (int kt = 0; kt <= ktmax; kt++) {
        // V_kt (overlaps QK); barrier first: prev PV must be done with V smem
        __syncthreads();
        {
            const size_t vo = koff0 + (size_t)kt*64*Dv;
            #pragma unroll
            for (int u = 0; u < 4; u++) {
                cp16(sb + VH +         drk + u*16, Vh + vo + u*8);
                cp16(sb + VH + KTILE + drk + u*16, Vl + vo + u*8);
            }
        }
        cp_commit();
        cp_wait<1>();        // K_kt (and Q) ready
        __syncthreads();

        // ---- scores: S[16 x 64] per warp over dk=128, hi/lo 3-term ----
        float sc[8][4];
        #pragma unroll
        for (int nt = 0; nt < 8; nt++)
            #pragma unroll
            for (int j = 0; j < 4; j++) sc[nt][j] = 0.0f;

        #pragma unroll
        for (int ks = 0; ks < 8; ks++) {
            uint32_t qh[4], ql[4];
            const uint32_t qaddr = sb + QH +
                (uint32_t)(((warp*16 + (lane & 15))*SP + ks*16 + (lane >> 4)*8) * 2);
            ldsm4(qaddr,         qh);
            ldsm4(qaddr + QTILE, ql);
            #pragma unroll
            for (int p = 0; p < 4; p++) {
                const uint32_t kaddr = sb + KH +
                    (uint32_t)(((p*16 + (lane & 15))*SP + ks*16 + (lane >> 4)*8) * 2);
                uint32_t th[4], tl[4];
                ldsm4(kaddr,         th);
                ldsm4(kaddr + KTILE, tl);
                uint32_t bh0[2] = {th[0], th[2]}, bh1[2] = {th[1], th[3]};
                uint32_t bl0[2] = {tl[0], tl[2]}, bl1[2] = {tl[1], tl[3]};
                mma16816(sc[2*p],   qh, bh0);
                mma16816(sc[2*p],   ql, bh0);
                mma16816(sc[2*p],   qh, bl0);
                mma16816(sc[2*p+1], qh, bh1);
                mma16816(sc[2*p+1], ql, bh1);
                mma16816(sc[2*p+1], qh, bl1);
            }
        }

        // ---- softmax ----
        const int gr0 = q0 + warp*16 + (lane >> 2);
        const int gr1 = gr0 + 8;
        if (kt >= 2*qt) {    // only the last two tiles can cross the diagonal
            #pragma unroll
            for (int nt = 0; nt < 8; nt++) {
                const int cb = kt*64 + nt*8 + (lane & 3)*2;
                if (cb     > gr0) sc[nt][0] = -1e30f;
                if (cb + 1 > gr0) sc[nt][1] = -1e30f;
                if (cb     > gr1) sc[nt][2] = -1e30f;
                if (cb + 1 > gr1) sc[nt][3] = -1e30f;
            }
        }
        float mx0 = -1e30f, mx1 = -1e30f;
        #pragma unroll
        for (int nt = 0; nt < 8; nt++) {
            mx0 = fmaxf(mx0, fmaxf(sc[nt][0], sc[nt][1]));
            mx1 = fmaxf(mx1, fmaxf(sc[nt][2], sc[nt][3]));
        }
        mx0 = fmaxf(mx0, __shfl_xor_sync(0xffffffffu, mx0, 1));
        mx0 = fmaxf(mx0, __shfl_xor_sync(0xffffffffu, mx0, 2));
        mx1 = fmaxf(mx1, __shfl_xor_sync(0xffffffffu, mx1, 1));
        mx1 = fmaxf(mx1, __shfl_xor_sync(0xffffffffu, mx1, 2));

        const float mn0 = fmaxf(m0, mx0), mn1 = fmaxf(m1, mx1);
        const float a0 = __expf(m0 - mn0), a1 = __expf(m1 - mn1);
        m0 = mn0; m1 = mn1;

        float s0 = 0.0f, s1 = 0.0f;
        #pragma unroll
        for (int nt = 0; nt < 8; nt++) {
            sc[nt][0] = __expf(sc[nt][0] - mn0);
            sc[nt][1] = __expf(sc[nt][1] - mn0);
            sc[nt][2] = __expf(sc[nt][2] - mn1);
            sc[nt][3] = __expf(sc[nt][3] - mn1);
            s0 += sc[nt][0] + sc[nt][1];
            s1 += sc[nt][2] + sc[nt][3];
        }
        s0 += __shfl_xor_sync(0xffffffffu, s0, 1);
        s0 += __shfl_xor_sync(0xffffffffu, s0, 2);
        s1 += __shfl_xor_sync(0xffffffffu, s1, 1);
        s1 += __shfl_xor_sync(0xffffffffu, s1, 2);
        l0 = l0 * a0 + s0;
        l1 = l1 * a1 + s1;

        #pragma unroll
        for (int nt = 0; nt < 16; nt++) {
            ctxa[nt][0] *= a0; ctxa[nt][1] *= a0;
            ctxa[nt][2] *= a1; ctxa[nt][3] *= a1;
        }

        // pack P (C-frag -> A-frag), hi/lo
        uint32_t pah[4][4], pal[4][4];
        #pragma unroll
        for (int k2 = 0; k2 < 4; k2++) {
            split2(sc[2*k2][0],   sc[2*k2][1],   pah[k2][0], pal[k2][0]);
            split2(sc[2*k2][2],   sc[2*k2][3],   pah[k2][1], pal[k2][1]);
            split2(sc[2*k2+1][0], sc[2*k2+1][1], pah[k2][2], pal[k2][2]);
            split2(sc[2*k2+1][2], sc[2*k2+1][3], pah[k2][3], pal[k2][3]);
        }

        // all warps done reading K smem -> start K_{kt+1}
        __syncthreads();
        if (kt < ktmax) {
            const size_t ko = koff0 + (size_t)(kt+1)*64*Dv;
            #pragma unroll
            for (int u = 0; u < 4; u++) {
                cp16(sb + KH +         drk + u*16, Kh + ko + u*8);
                cp16(sb + KH + KTILE + drk + u*16, Kl + ko + u*8);
            }
        }
        cp_commit();          // unconditional: keeps group numbering exact
        cp_wait<1>();         // V_kt ready
        __syncthreads();

        // ---- ctx += P @ V  (V via ldmatrix.trans) ----
        #pragma unroll
        for (int k2 = 0; k2 < 4; k2++) {
            #pragma unroll
            for (int p = 0; p < 8; p++) {
                const uint32_t vaddr = sb + VH +
                    (uint32_t)(((k2*16 + (lane & 15))*SP + p*16 + (lane >> 4)*8) * 2);
                uint32_t vh[4], vl[4];
                ldsm4t(vaddr,         vh);
                ldsm4t(vaddr + KTILE, vl);
                uint32_t bh0[2] = {vh[0], vh[1]}, bh1[2] = {vh[2], vh[3]};
                uint32_t bl0[2] = {vl[0], vl[1]}, bl1[2] = {vl[2], vl[3]};
                mma16816(ctxa[2*p],   pah[k2], bh0);
                mma16816(ctxa[2*p],   pal[k2], bh0);
                mma16816(ctxa[2*p],   pah[k2], bl0);
                mma16816(ctxa[2*p+1], pah[k2], bh1);
                mma16816(ctxa[2*p+1], pal[k2], bh1);
                mma16816(ctxa[2*p+1], pah[k2], bl1);
            }
        }
    }

    // epilogue: ctx/l -> bf16 hi/lo planes
    const float i0 = 1.0f / l0, i1 = 1.0f / l1;
    const size_t r0g = (size_t)(b*Sv + q0 + warp*16 + (lane >> 2));
    const size_t r1g = r0g + 8;
    #pragma unroll
    for (int nt = 0; nt < 16; nt++) {
        const size_t col = hoff + nt*8 + (lane & 3)*2;
        uint32_t h0, l0u, h1, l1u;
        split2(ctxa[nt][0]*i0, ctxa[nt][1]*i0, h0, l0u);
        split2(ctxa[nt][2]*i1, ctxa[nt][3]*i1, h1, l1u);
        *(uint32_t*)(ch + r0g*Dv + col) = h0;
        *(uint32_t*)(cl + r0g*Dv + col) = l0u;
        *(uint32_t*)(ch + r1g*Dv + col) = h1;
        *(uint32_t*)(cl + r1g*Dv + col) = l1u;
    }
}

// ---------------------------------------------------------------------------
extern "C" void kernel_launch(void* const* d_in, const int* in_sizes, int n_in,
                              void* d_out, int out_size)
{
    const float* x  = (const float*)d_in[0];
    const float* fc = (const float*)d_in[1];
    const float* fs = (const float*)d_in[2];
    // d_in[3] = mask (unused: -1e9 mask == strict causal in f32)
    const float* Wq = (const float*)d_in[4];
    const float* Wk = (const float*)d_in[5];
    const float* Wv = (const float*)d_in[6];
    const float* Wo = (const float*)d_in[7];

    float* out  = (float*)d_out;
    float* outK = out  + (size_t)Mv*Dv;
    float* outV = outK + (size_t)Mv*Dv;

    __nv_bfloat16 *xh, *xl, *wh, *wl, *qh, *ql, *kh, *kl, *vh, *vl, *ch, *cl;
    cudaGetSymbolAddress((void**)&xh, g_xh);
    cudaGetSymbolAddress((void**)&xl, g_xl);
    cudaGetSymbolAddress((void**)&wh, g_wh);
    cudaGetSymbolAddress((void**)&wl, g_wl);
    cudaGetSymbolAddress((void**)&qh, g_qh);
    cudaGetSymbolAddress((void**)&ql, g_ql);
    cudaGetSymbolAddress((void**)&kh, g_kh);
    cudaGetSymbolAddress((void**)&kl, g_kl);
    cudaGetSymbolAddress((void**)&vh, g_vh);
    cudaGetSymbolAddress((void**)&vl, g_vl);
    cudaGetSymbolAddress((void**)&ch, g_ch);
    cudaGetSymbolAddress((void**)&cl, g_cl);

    cudaFuncSetAttribute(gemm_qkv, cudaFuncAttributeMaxDynamicSharedMemorySize, GSM_TOTAL);
    cudaFuncSetAttribute(gemm_wo,  cudaFuncAttributeMaxDynamicSharedMemorySize, GSM_TOTAL);
    cudaFuncSetAttribute(attn_mma, cudaFuncAttributeMaxDynamicSharedMemorySize, ASM_TOT);

    const size_t WN = (size_t)Dv*Dv;     // 4M elems per weight

    split_x<<<(Mv*Dv/8 + 255)/256, 256>>>(x, xh, xl, Mv*Dv/8);
    split_w4<<<(int)(4*WN/8/256), 256>>>(Wq, Wk, Wv, Wo, wh, wl);

    dim3 ggrid(Dv/128, Mv/128, 3);   // (16, 32, 3)
    gemm_qkv<<<ggrid, 256, GSM_TOTAL>>>(xh, xl, wh, wl, fc, fs, outK, outV,
                                        qh, ql, kh, kl, vh, vl);

    attn_mma<<<dim3(Sv/128, Hv, Bv), 256, ASM_TOT>>>(qh, ql, kh, kl, vh, vl, ch, cl);

    gemm_wo<<<dim3(Dv/128, Mv/128), 256, GSM_TOTAL>>>(ch, cl, wh + 3*WN, wl + 3*WN, out);
}